// round 14
// baseline (speedup 1.0000x reference)
#include <cuda_runtime.h>
#include <cuda_bf16.h>
#include <math.h>
#include <stdint.h>

#define BB    16
#define CCH   512
#define NN    3136
#define NKK   49
#define HEADS 8
#define JJ    392
#define HIDC  24
#define SCALE 0.125f

// ---------------- device scratch ----------------
__device__ float g_kvx[BB*NKK*CCH];
__device__ float g_kv [BB*NKK*1024];
__device__ float g_Wvp[BB*JJ*CCH];
__device__ __nv_bfloat16 g_xTh[(size_t)BB*NN*CCH];
__device__ __nv_bfloat16 g_xTl[(size_t)BB*NN*CCH];
__device__ __nv_bfloat16 g_wqh[BB*JJ*CCH];
__device__ __nv_bfloat16 g_wvh[BB*CCH*JJ];
__device__ __nv_bfloat16 g_wvl[BB*CCH*JJ];
__device__ float g_attn[(size_t)BB*NN*JJ];
__device__ __nv_bfloat16 g_ath[(size_t)BB*NN*JJ];
__device__ __nv_bfloat16 g_atl[(size_t)BB*NN*JJ];
__device__ float g_part1[BB*98*36];
__device__ float g_part2[BB*3*196*2];
__device__ float g_part3[BB*392*2];
__device__ float g_ab1[BB*HIDC*2];
__device__ float g_bias2[BB*CCH];

__device__ __forceinline__ float swishf(float x) { return x / (1.f + __expf(-x)); }

__device__ __forceinline__ void bsplit(float v, __nv_bfloat16& h, __nv_bfloat16& l) {
    h = __float2bfloat16(v);
    l = __float2bfloat16(v - __bfloat162float(h));
}

__device__ __forceinline__ uint32_t smem_u32(const void* p) {
    uint32_t a;
    asm("{ .reg .u64 t; cvta.to.shared.u64 t, %1; cvt.u32.u64 %0, t; }" : "=r"(a) : "l"(p));
    return a;
}
__device__ __forceinline__ void ldm_x4(uint32_t* r, uint32_t addr) {
    asm volatile("ldmatrix.sync.aligned.m8n8.x4.shared.b16 {%0,%1,%2,%3}, [%4];"
        : "=r"(r[0]), "=r"(r[1]), "=r"(r[2]), "=r"(r[3]) : "r"(addr));
}
__device__ __forceinline__ void ldm_x2(uint32_t* r, uint32_t addr) {
    asm volatile("ldmatrix.sync.aligned.m8n8.x2.shared.b16 {%0,%1}, [%2];"
        : "=r"(r[0]), "=r"(r[1]) : "r"(addr));
}
__device__ __forceinline__ void mma_bf16(float* c, const uint32_t* a, const uint32_t* b) {
    asm volatile(
        "mma.sync.aligned.m16n8k16.row.col.f32.bf16.bf16.f32 "
        "{%0,%1,%2,%3}, {%4,%5,%6,%7}, {%8,%9}, {%0,%1,%2,%3};"
        : "+f"(c[0]), "+f"(c[1]), "+f"(c[2]), "+f"(c[3])
        : "r"(a[0]), "r"(a[1]), "r"(a[2]), "r"(a[3]), "r"(b[0]), "r"(b[1]));
}
__device__ __forceinline__ void cpa16(uint32_t dst, const void* src, bool v) {
    int sz = v ? 16 : 0;
    asm volatile("cp.async.cg.shared.global [%0], [%1], 16, %2;"
        :: "r"(dst), "l"(src), "r"(sz) : "memory");
}
__device__ __forceinline__ void cp_commit() {
    asm volatile("cp.async.commit_group;" ::: "memory");
}
__device__ __forceinline__ void cp_wait1() {
    asm volatile("cp.async.wait_group 1;" ::: "memory");
}
__device__ __forceinline__ void cp_wait0() {
    asm volatile("cp.async.wait_group 0;" ::: "memory");
}

// ---------------- 1. k_prep: fused xsplit + down ----------------
__global__ __launch_bounds__(256) void k_prep(const float* __restrict__ x,
                                              const float* __restrict__ down_w) {
    __shared__ float sh[3200];
    int blk = blockIdx.x;
    int t = threadIdx.x;
    if (blk < 25088) {
        int tn = blk % 98;
        int rest = blk / 98;
        int tc = rest & 15, b = rest >> 4;
        float (*tile)[33] = (float(*)[33])sh;
        int a = t >> 5, q = t & 31;
        #pragma unroll
        for (int r = 0; r < 4; r++) {
            int cc = tc*32 + a + r*8, nn = tn*32 + q;
            tile[a + r*8][q] = x[((size_t)b*512 + cc)*3136 + nn];
        }
        __syncthreads();
        #pragma unroll
        for (int r = 0; r < 4; r++) {
            int nn = tn*32 + a + r*8, cc = tc*32 + q;
            float v = tile[q][a + r*8];
            __nv_bfloat16 h, l; bsplit(v, h, l);
            size_t o = ((size_t)b*3136 + nn)*512 + cc;
            g_xTh[o] = h; g_xTl[o] = l;
        }
    } else {
        int bc = blk - 25088, c = bc & 511, b = bc >> 9;
        float* plane = sh;
        float* w = sh + 3136;
        const float* xp = x + (size_t)bc * 3136;
        for (int i = t; i < 3136; i += 256) plane[i] = xp[i];
        if (t < 64) w[t] = down_w[c*64 + t];
        __syncthreads();
        if (t < 49) {
            int my = t / 7, mx = t % 7;
            float s = 0.f;
            #pragma unroll
            for (int i = 0; i < 8; i++)
                #pragma unroll
                for (int j = 0; j < 8; j++)
                    s += plane[(my*8+i)*56 + mx*8 + j] * w[i*8+j];
            g_kvx[(b*49 + t)*512 + c] = s;
        }
    }
}

// ---------------- 2. kv = kvx @ kv_w ----------------
__global__ void k_kv(const float* __restrict__ kv_w) {
    int b = blockIdx.z, m0 = blockIdx.y * 7, oc = blockIdx.x;
    __shared__ float a[7][512];
    for (int i = threadIdx.x; i < 7*512; i += 256)
        a[i >> 9][i & 511] = g_kvx[(b*49 + m0 + (i >> 9))*512 + (i & 511)];
    __syncthreads();
    int o = oc*256 + threadIdx.x;
    float acc[7] = {0,0,0,0,0,0,0};
    for (int c = 0; c < 512; c++) {
        float w = kv_w[c*1024 + o];
        #pragma unroll
        for (int mm = 0; mm < 7; mm++) acc[mm] += a[mm][c] * w;
    }
    #pragma unroll
    for (int mm = 0; mm < 7; mm++)
        g_kv[(b*49 + m0 + mm)*1024 + o] = acc[mm];
}

// ---------------- 3. k_qkvw: fused wqk_split + wvp ----------------
__global__ __launch_bounds__(256) void k_qkvw(const float* __restrict__ q_w,
                                              const float* __restrict__ proj_w) {
    __shared__ float sh[3136];
    int blk = blockIdx.x;
    int t = threadIdx.x;
    if (blk < 256) {
        int half = blk & 1, h = (blk >> 1) & 7, b = blk >> 4;
        float (*ks)[64] = (float(*)[64])sh;
        for (int i = t; i < 49*64; i += 256)
            ks[i >> 6][i & 63] = g_kv[(b*49 + (i >> 6))*1024 + h*64 + (i & 63)];
        __syncthreads();
        int cin = half*256 + t;
        float acc[49];
        #pragma unroll
        for (int m = 0; m < 49; m++) acc[m] = 0.f;
        const float4* q4 = (const float4*)(q_w + (size_t)cin*512 + h*64);
        const float4* ks4 = (const float4*)&ks[0][0];
        for (int d4 = 0; d4 < 16; d4++) {
            float4 q = __ldg(q4 + d4);
            #pragma unroll
            for (int m = 0; m < 49; m++) {
                float4 k = ks4[m*16 + d4];
                acc[m] += q.x*k.x + q.y*k.y + q.z*k.z + q.w*k.w;
            }
        }
        size_t obase = ((size_t)b*392 + h*49)*512 + cin;
        #pragma unroll
        for (int m = 0; m < 49; m++)
            g_wqh[obase + (size_t)m*512] = __float2bfloat16(acc[m] * SCALE);
    } else {
        int q = blk - 256;
        int mc = (q % 7) * 7, h = (q / 7) & 7, b = q / 56;
        float (*vs)[64] = (float(*)[64])sh;
        for (int i = t; i < 7*64; i += 256)
            vs[i >> 6][i & 63] = g_kv[(b*49 + mc + (i >> 6))*1024 + 512 + h*64 + (i & 63)];
        __syncthreads();
        float acc[7][2] = {{0}};
        for (int d = 0; d < 64; d++) {
            float w0 = proj_w[(h*64+d)*512 + t];
            float w1 = proj_w[(h*64+d)*512 + 256 + t];
            #pragma unroll
            for (int mm = 0; mm < 7; mm++) {
                float vv = vs[mm][d];
                acc[mm][0] += vv * w0;
                acc[mm][1] += vv * w1;
            }
        }
        #pragma unroll
        for (int mm = 0; mm < 7; mm++) {
            int j = h*49 + mc + mm;
            g_Wvp[(b*392 + j)*512 + t]       = acc[mm][0];
            g_Wvp[(b*392 + j)*512 + 256 + t] = acc[mm][1];
        }
    }
}

// ---------------- 4. GEMM1 fused (bf16x2; 32n x 416j tiles, k-tile 32, 2 CTAs/SM) ----------------
#define G1_BUFSZ 38400u
#define G1_AHOFF 0u
#define G1_ALOFF 2560u
#define G1_BHOFF 5120u
#define G1_SMEM  76800
__device__ __forceinline__ void g1f_load(uint32_t sb, int b, int nt0, int kt, int p, int t) {
    int k0 = kt*32;
    uint32_t base = sb + (uint32_t)p*G1_BUFSZ;
    {
        int hl = t >= 128;
        int ii = t & 127;
        int row = ii >> 2, q = ii & 3;
        size_t e = ((size_t)b*3136 + nt0 + row)*512 + k0 + q*8;
        uint32_t doff = (uint32_t)(row*40 + q*8)*2;
        cpa16(base + (hl ? G1_ALOFF : G1_AHOFF) + doff, (hl ? g_xTl : g_xTh) + e, true);
    }
    #pragma unroll
    for (int rr = 0; rr < 7; rr++) {
        int idx = rr*256 + t;
        if (idx < 1664) {
            int row = idx >> 2, q = idx & 3;
            bool v = row < 392;
            size_t e = ((size_t)b*392 + (v ? row : 0))*512 + k0 + q*8;
            uint32_t doff = (uint32_t)(row*40 + q*8)*2;
            cpa16(base + G1_BHOFF + doff, g_wqh + e, v);
        }
    }
}

__global__ __launch_bounds__(256, 2) void k_gemm1_fused(const float* __restrict__ rel_bias) {
    extern __shared__ char smraw[];
    uint32_t sb = smem_u32(smraw);
    int b = blockIdx.y, nt0 = blockIdx.x * 32;
    int t = threadIdx.x, w = t >> 5, lane = t & 31;
    int wn = (w & 1)*16, wj = (w >> 1)*104;
    float acc[13][4];
    #pragma unroll
    for (int j = 0; j < 13; j++)
        #pragma unroll
        for (int k = 0; k < 4; k++) acc[j][k] = 0.f;

    g1f_load(sb, b, nt0, 0, 0, t);
    cp_commit();
    for (int kt = 0; kt < 16; kt++) {
        if (kt < 15) {
            g1f_load(sb, b, nt0, kt+1, (kt+1) & 1, t);
            cp_commit();
            cp_wait1();
        } else cp_wait0();
        __syncthreads();
        uint32_t base = sb + (uint32_t)(kt & 1)*G1_BUFSZ;
        #pragma unroll
        for (int kk = 0; kk < 2; kk++) {
            int kb = kk*16;
            uint32_t ah[4], al[4];
            int arow = wn + (lane & 15);
            int acol = kb + ((lane & 16) ? 8 : 0);
            ldm_x4(ah, base + G1_AHOFF + (uint32_t)(arow*40 + acol)*2);
            ldm_x4(al, base + G1_ALOFF + (uint32_t)(arow*40 + acol)*2);
            #pragma unroll
            for (int p2 = 0; p2 < 6; p2++) {
                int jrow = wj + p2*16 + (lane & 7) + ((lane & 16) ? 8 : 0);
                int col = kb + ((lane & 8) ? 8 : 0);
                uint32_t off = (uint32_t)(jrow*40 + col)*2;
                uint32_t rh[4];
                ldm_x4(rh, base + G1_BHOFF + off);
                #pragma unroll
                for (int e = 0; e < 2; e++) {
                    mma_bf16(acc[2*p2+e], ah, &rh[2*e]);
                    mma_bf16(acc[2*p2+e], al, &rh[2*e]);
                }
            }
            {
                int jrow = wj + 96 + (lane & 7);
                int col = kb + ((lane & 8) ? 8 : 0);
                uint32_t off = (uint32_t)(jrow*40 + col)*2;
                uint32_t bh2[2];
                ldm_x2(bh2, base + G1_BHOFF + off);
                mma_bf16(acc[12], ah, bh2);
                mma_bf16(acc[12], al, bh2);
            }
        }
        __syncthreads();
    }
    float* S = (float*)smraw;
    float* Gred = S + 32*400;
    {
        int nl = wn + (lane >> 2);
        #pragma unroll
        for (int jt = 0; jt < 13; jt++) {
            int j0 = wj + jt*8 + ((lane & 3) << 1);
            if (j0 < 392) {
                S[nl*400 + j0]       = acc[jt][0];
                S[nl*400 + j0 + 1]   = acc[jt][1];
                S[(nl+8)*400 + j0]   = acc[jt][2];
                S[(nl+8)*400 + j0+1] = acc[jt][3];
            }
        }
    }
    __syncthreads();
    {
        int n = t >> 3, h = t & 7;
        float* p = S + n*400 + h*49;
        const float* rb = rel_bias + (size_t)(nt0 + n)*49;
        float mx = -1e30f;
        for (int i = 0; i < 49; i++) {
            float lv = p[i] + __ldg(rb + i);
            p[i] = lv;
            mx = fmaxf(mx, lv);
        }
        float sum = 0.f;
        for (int i = 0; i < 49; i++) { float e = __expf(p[i] - mx); p[i] = e; sum += e; }
        float inv = 1.f / sum;
        for (int i = 0; i < 49; i++) p[i] *= inv;
    }
    __syncthreads();
    float g[36];
    #pragma unroll
    for (int k = 0; k < 36; k++) g[k] = 0.f;
    for (int pos = t; pos < 32*49; pos += 256) {
        int n = pos / 49, m = pos - n*49;
        float a[8];
        #pragma unroll
        for (int h = 0; h < 8; h++) a[h] = S[n*400 + h*49 + m];
        int k = 0;
        #pragma unroll
        for (int h = 0; h < 8; h++)
            #pragma unroll
            for (int h2 = h; h2 < 8; h2++) { g[k] += a[h]*a[h2]; k++; }
    }
    size_t ob = ((size_t)b*3136 + nt0)*392;
    for (int i = t; i < 32*392; i += 256) {
        int n = i / 392, c = i - n*392;
        g_attn[ob + i] = S[n*400 + c];
    }
    #pragma unroll
    for (int s = 16; s; s >>= 1)
        #pragma unroll
        for (int k = 0; k < 36; k++) g[k] += __shfl_xor_sync(0xffffffffu, g[k], s);
    if (lane == 0)
        #pragma unroll
        for (int k = 0; k < 36; k++) Gred[w*36 + k] = g[k];
    __syncthreads();
    if (t < 36) {
        float s = 0.f;
        #pragma unroll
        for (int ww = 0; ww < 8; ww++) s += Gred[ww*36 + t];
        g_part1[((size_t)b*98 + blockIdx.x)*36 + t] = s;
    }
}

// ---------------- 5. pass B: inline gn1 + expand+dw -> gn2 partials ----------------
#define B_AT  0
#define B_HID 7056
#define B_EW  14416
#define B_AB  14608
#define B_RED 14656
#define B_TOT (14656 + 1536)
#define B_SMEM (B_TOT*4)
__global__ __launch_bounds__(256) void k_dw_gn2(const float* __restrict__ dw_w,
                                                const float* __restrict__ expand_w,
                                                const float* __restrict__ gs1,
                                                const float* __restrict__ gb1) {
    extern __shared__ float sm[];
    float* at  = sm + B_AT;
    float* ew  = sm + B_EW;
    float* ab  = sm + B_AB;
    float* red = sm + B_RED;
    int nt = blockIdx.x, b = blockIdx.y, t = threadIdx.x;
    int w = t >> 5, lane = t & 31;
    float* hid = sm + B_HID + w*920;
    int n0 = nt * 16;
    if (t < 192) ew[t] = expand_w[t];
    __syncthreads();
    // ---- inline gn1 finalize (identical order to old k_gn1_final) ----
    {
        float* M   = red;        // 36
        float* Mf  = red + 64;   // 64
        float* s1s = red + 128;  // 24
        float* sqs = red + 160;  // 24
        float* mr  = red + 192;  // 6
        if (t < 36) {
            float s = 0.f;
            for (int q = 0; q < 98; q++) s += g_part1[((size_t)b*98 + q)*36 + t];
            M[t] = s;
        }
        __syncthreads();
        if (t == 0) {
            int k = 0;
            for (int h = 0; h < 8; h++)
                for (int h2 = h; h2 < 8; h2++) { Mf[h*8+h2] = M[k]; Mf[h2*8+h] = M[k]; k++; }
        }
        __syncthreads();
        if (t < 24) {
            float wv[8], sw = 0.f;
            #pragma unroll
            for (int h = 0; h < 8; h++) { wv[h] = ew[t*8+h]; sw += wv[h]; }
            float sq = 0.f;
            #pragma unroll
            for (int h = 0; h < 8; h++)
                #pragma unroll
                for (int h2 = 0; h2 < 8; h2++) sq += wv[h]*wv[h2]*Mf[h*8+h2];
            s1s[t] = 3136.f * sw;
            sqs[t] = sq;
        }
        __syncthreads();
        if (t < 3) {
            float s1 = 0.f, sq = 0.f;
            for (int c = 0; c < 8; c++) { s1 += s1s[t*8+c]; sq += sqs[t*8+c]; }
            float cnt = 8.f*3136.f*49.f;
            float mean = s1/cnt;
            float var  = sq/cnt - mean*mean;
            mr[t] = mean;
            mr[3+t] = rsqrtf(var + 1e-5f);
        }
        __syncthreads();
        if (t < 24) {
            float A = mr[3+(t>>3)]*gs1[t];
            ab[t*2]     = A;
            ab[t*2 + 1] = gb1[t] - mr[t>>3]*A;
        }
        __syncthreads();
        if (t < 48) g_ab1[b*48 + t] = ab[t];   // identical values from all blocks
    }
    for (int i = t; i < 18*392; i += 256) {
        int r = i / 392, m = i - r*392;
        int n = n0 - 1 + r;
        at[i] = (n >= 0 && n < 3136) ? g_attn[((size_t)b*3136 + n)*392 + m] : 0.f;
    }
    __syncthreads();
    float sk[3] = {0,0,0}, qk[3] = {0,0,0};
    #pragma unroll
    for (int k = 0; k < 3; k++) {
        int c = w + k*8;
        float A1 = ab[c*2], B1 = ab[c*2+1];
        const float* wp = ew + c*8;
        for (int i = lane; i < 918; i += 32) {
            int r = i / 51, mm = i - r*51;
            int n = n0 - 1 + r;
            float v = 0.f;
            if (mm >= 1 && mm <= 49 && n >= 0 && n < 3136) {
                const float* sp = at + r*392 + (mm - 1);
                float hsum = 0.f;
                #pragma unroll
                for (int hh = 0; hh < 8; hh++) hsum += sp[hh*49] * wp[hh];
                v = swishf(A1*hsum + B1);
            }
            hid[i] = v;
        }
        __syncwarp();
        float lw[9];
        #pragma unroll
        for (int i = 0; i < 9; i++) lw[i] = dw_w[c*9 + i];
        for (int o = lane; o < 784; o += 32) {
            int ny = o / 49, m = o - ny*49;
            float a = 0.f;
            #pragma unroll
            for (int dy = 0; dy < 3; dy++)
                #pragma unroll
                for (int dx = 0; dx < 3; dx++)
                    a += hid[(ny+dy)*51 + m+dx] * lw[dy*3+dx];
            sk[k] += a; qk[k] += a*a;
        }
        __syncwarp();
    }
    #pragma unroll
    for (int g = 0; g < 3; g++) { red[g*256 + t] = sk[g]; red[(3+g)*256 + t] = qk[g]; }
    __syncthreads();
    for (int st = 128; st; st >>= 1) {
        if (t < st)
            #pragma unroll
            for (int g = 0; g < 6; g++) red[g*256 + t] += red[g*256 + t + st];
        __syncthreads();
    }
    if (t < 3) {
        g_part2[((b*3 + t)*196 + nt)*2]     = red[t*256];
        g_part2[((b*3 + t)*196 + nt)*2 + 1] = red[(t+3)*256];
    }
}

// ---------------- 6. pass C: inline gn2 + expand+dw+norm2+swish, reduce -> attnF + gn3 ----------------
#define C_AT  0
#define C_HID 3920
#define C_DWS 8016
#define C_EW  17424
#define C_RW  17616
#define C_AB  17808
#define C_RED 17904
#define C_TOT (17904 + 512)
#define C_SMEM (C_TOT*4)
__global__ __launch_bounds__(256) void k_dla_out(const float* __restrict__ dw_w,
                                                 const float* __restrict__ expand_w,
                                                 const float* __restrict__ reduce_w,
                                                 const float* __restrict__ gs2,
                                                 const float* __restrict__ gb2) {
    extern __shared__ float sm[];
    float* at  = sm + C_AT;
    float* dws = sm + C_DWS;
    float* ew  = sm + C_EW;
    float* rw  = sm + C_RW;
    float* ab  = sm + C_AB;
    float* red = sm + C_RED;
    int nt = blockIdx.x, b = blockIdx.y, t = threadIdx.x;
    int w = t >> 5, lane = t & 31;
    float* hid = sm + C_HID + w*512;
    int n0 = nt * 8;
    if (t < 192) { ew[t] = expand_w[t]; rw[t] = reduce_w[t]; }
    if (t < 48) ab[t] = g_ab1[b*48 + t];
    // ---- inline gn2 finalize: 3 warps, one per group ----
    if (w < 3) {
        const float* p2 = g_part2 + (size_t)(b*3 + w)*196*2;
        float smv = 0.f, sq = 0.f;
        for (int i = lane; i < 196; i += 32) { smv += p2[2*i]; sq += p2[2*i+1]; }
        #pragma unroll
        for (int s = 16; s; s >>= 1) {
            smv += __shfl_xor_sync(0xffffffffu, smv, s);
            sq  += __shfl_xor_sync(0xffffffffu, sq, s);
        }
        if (lane == 0) {
            float cnt = 8.f*3136.f*49.f;
            float mean = smv/cnt;
            float var  = sq/cnt - mean*mean;
            float rstd = rsqrtf(var + 1e-5f);
            for (int c0 = 0; c0 < 8; c0++) {
                int c = w*8 + c0;
                float A = rstd * gs2[c];
                ab[48 + c*2] = A;
                ab[49 + c*2] = gb2[c] - mean*A;
            }
        }
    }
    for (int i = t; i < 10*392; i += 256) {
        int r = i / 392, m = i - r*392;
        int n = n0 - 1 + r;
        at[i] = (n >= 0 && n < 3136) ? g_attn[((size_t)b*3136 + n)*392 + m] : 0.f;
    }
    __syncthreads();
    #pragma unroll
    for (int k = 0; k < 3; k++) {
        int c = w + k*8;
        float A1 = ab[c*2], B1 = ab[c*2+1];
        float A2 = ab[48 + c*2], B2 = ab[49 + c*2];
        const float* wp = ew + c*8;
        for (int i = lane; i < 510; i += 32) {
            int r = i / 51, mm = i - r*51;
            int n = n0 - 1 + r;
            float v = 0.f;
            if (mm >= 1 && mm <= 49 && n >= 0 && n < 3136) {
                const float* sp = at + r*392 + (mm - 1);
                float hsum = 0.f;
                #pragma unroll
                for (int hh = 0; hh < 8; hh++) hsum += sp[hh*49] * wp[hh];
                v = swishf(A1*hsum + B1);
            }
            hid[i] = v;
        }
        __syncwarp();
        float lw[9];
        #pragma unroll
        for (int i = 0; i < 9; i++) lw[i] = dw_w[c*9 + i];
        for (int o = lane; o < 392; o += 32) {
            int ny = o / 49, m = o - ny*49;
            float a = 0.f;
            #pragma unroll
            for (int dy = 0; dy < 3; dy++)
                #pragma unroll
                for (int dx = 0; dx < 3; dx++)
                    a += hid[(ny+dy)*51 + m+dx] * lw[dy*3+dx];
            dws[(ny*24 + c)*49 + m] = swishf(A2*a + B2);
        }
        __syncwarp();
    }
    __syncthreads();
    float lsum = 0.f, lsq = 0.f;
    for (int o = t; o < 392; o += 256) {
        int ny = o / 49, m = o - ny*49;
        int n = n0 + ny;
        float in[24];
        #pragma unroll
        for (int c = 0; c < 24; c++) in[c] = dws[(ny*24 + c)*49 + m];
        size_t ob = ((size_t)b*3136 + n)*392 + m;
        #pragma unroll
        for (int h = 0; h < 8; h++) {
            float r = 0.f;
            #pragma unroll
            for (int c = 0; c < 24; c++) r += in[c] * rw[h*24 + c];
            __nv_bfloat16 hh, ll; bsplit(r, hh, ll);
            g_ath[ob + h*49] = hh;
            g_atl[ob + h*49] = ll;
            lsum += r; lsq += r*r;
        }
    }
    red[t] = lsum; red[256 + t] = lsq;
    __syncthreads();
    for (int st = 128; st; st >>= 1) {
        if (t < st) { red[t] += red[t+st]; red[256+t] += red[256+t+st]; }
        __syncthreads();
    }
    if (!t) {
        g_part3[(b*392 + nt)*2]     = red[0];
        g_part3[(b*392 + nt)*2 + 1] = red[256];
    }
}

// ---------------- 7. k_wvpfin: inline gn3 + wvpsplit (0..3327) + wvpbias (3328..3343) ----------------
__global__ __launch_bounds__(256) void k_wvpfin(const float* __restrict__ proj_b,
                                                const float* __restrict__ gs3,
                                                const float* __restrict__ gb3) {
    __shared__ float tile[32][33];
    __shared__ float ab3s[16];
    int blk = blockIdx.x;
    int t = threadIdx.x;
    int w = t >> 5, lane = t & 31;
    int b = (blk < 3328) ? ((blk / 13) >> 4) : (blk - 3328);
    // ---- inline gn3 finalize (warp 0) ----
    if (w == 0) {
        const float* p3 = g_part3 + (size_t)b*392*2;
        float smv = 0.f, sq = 0.f;
        for (int i = lane; i < 392; i += 32) { smv += p3[2*i]; sq += p3[2*i+1]; }
        #pragma unroll
        for (int s = 16; s; s >>= 1) {
            smv += __shfl_xor_sync(0xffffffffu, smv, s);
            sq  += __shfl_xor_sync(0xffffffffu, sq, s);
        }
        if (lane == 0) {
            float cnt = 8.f*3136.f*49.f;
            float mean = smv/cnt;
            float var  = sq/cnt - mean*mean;
            float rstd = rsqrtf(var + 1e-5f);
            for (int h = 0; h < 8; h++) {
                float A = rstd * gs3[h];
                ab3s[h*2]     = A;
                ab3s[h*2 + 1] = gb3[h] - mean*A;
            }
        }
    }
    __syncthreads();
    if (blk < 3328) {
        int tj = blk % 13;
        int rest = blk / 13;
        int tc = rest & 15;
        int a = w, q = lane;
        #pragma unroll
        for (int r = 0; r < 4; r++) {
            int jj = tj*32 + a + r*8, cc = tc*32 + q;
            float v = 0.f;
            if (jj < 392) v = g_Wvp[((size_t)b*392 + jj)*512 + cc] * ab3s[(jj/49)*2];
            tile[a + r*8][q] = v;
        }
        __syncthreads();
        #pragma unroll
        for (int r = 0; r < 4; r++) {
            int cc = tc*32 + a + r*8, jj = tj*32 + q;
            if (jj < 392) {
                float v = tile[q][a + r*8];
                __nv_bfloat16 h, l; bsplit(v, h, l);
                size_t o = ((size_t)b*512 + cc)*392 + jj;
                g_wvh[o] = h; g_wvl[o] = l;
            }
        }
    } else {
        #pragma unroll
        for (int cc = 0; cc < 2; cc++) {
            int c = t + cc*256;
            float acc = 0.f;
            for (int j = 0; j < 392; j++)
                acc += ab3s[(j/49)*2 + 1] * g_Wvp[((size_t)b*392 + j)*512 + c];
            g_bias2[b*512 + c] = acc + proj_b[c];
        }
    }
}

// ---------------- 8. GEMM2 (bf16x3 mma.sync, 2 CTAs/SM) ----------------
#define G2_BUF 15360
#define G2_AH 0
#define G2_AL 5120
#define G2_BH 10240
#define G2_BL 12800
#define G2_SMEM (G2_BUF*2*2)
__device__ __forceinline__ void g2_load(uint32_t sb, int b, int nt0, int ct0,
                                        int kt, int p, int t) {
    int k0 = kt*32;
    uint32_t base = sb + (uint32_t)p*G2_BUF*2;
    #pragma unroll
    for (int rr = 0; rr < 2; rr++) {
        int idx = t + rr*256;
        int row = idx >> 2, q = idx & 3;
        int n = nt0 + row, j0 = k0 + q*8;
        bool v = (n < 3136) && (j0 < 392);
        size_t e = ((size_t)b*3136 + (n < 3136 ? n : 0))*392 + (j0 < 392 ? j0 : 0);
        uint32_t doff = (uint32_t)(row*40 + q*8)*2;
        cpa16(base + G2_AH*2 + doff, g_ath + e, v);
        cpa16(base + G2_AL*2 + doff, g_atl + e, v);
    }
    {
        int idx = t;
        int row = idx >> 2, q = idx & 3;
        int c = ct0 + row, j0 = k0 + q*8;
        bool v = j0 < 392;
        size_t e = ((size_t)b*512 + c)*392 + (v ? j0 : 0);
        uint32_t doff = (uint32_t)(row*40 + q*8)*2;
        cpa16(base + G2_BH*2 + doff, g_wvh + e, v);
        cpa16(base + G2_BL*2 + doff, g_wvl + e, v);
    }
}

__global__ __launch_bounds__(256, 2) void k_gemm2_mma(float* __restrict__ out) {
    extern __shared__ __nv_bfloat16 dsm2[];
    uint32_t sb = smem_u32(dsm2);
    int b = blockIdx.z, nt0 = blockIdx.y*128, ct0 = blockIdx.x*64;
    int t = threadIdx.x, w = t >> 5, lane = t & 31;
    int wn = (w & 3)*32, wc = (w >> 2)*32;
    float acc[2][4][4];
    #pragma unroll
    for (int i = 0; i < 2; i++)
        #pragma unroll
        for (int j = 0; j < 4; j++)
            #pragma unroll
            for (int k = 0; k < 4; k++) acc[i][j][k] = 0.f;

    g2_load(sb, b, nt0, ct0, 0, 0, t);
    cp_commit();
    for (int kt = 0; kt < 13; kt++) {
        if (kt < 12) {
            g2_load(sb, b, nt0, ct0, kt+1, (kt+1) & 1, t);
            cp_commit();
            cp_wait1();
        } else cp_wait0();
        __syncthreads();
        uint32_t base = sb + (uint32_t)(kt & 1)*G2_BUF*2;
        #pragma unroll
        for (int kk = 0; kk < 2; kk++) {
            int kb = kk*16;
            uint32_t ah[2][4], al[2][4];
            #pragma unroll
            for (int mt = 0; mt < 2; mt++) {
                int row = wn + mt*16 + (lane & 15);
                int col = kb + ((lane & 16) ? 8 : 0);
                uint32_t off = (uint32_t)(row*40 + col)*2;
                ldm_x4(ah[mt], base + G2_AH*2 + off);
                ldm_x4(al[mt], base + G2_AL*2 + off);
            }
            uint32_t bh[4][2], bl[4][2];
            #pragma unroll
            for (int p = 0; p < 2; p++) {
                int crow = wc + p*16 + (lane & 7) + ((lane & 16) ? 8 : 0);
                int col = kb + ((lane & 8) ? 8 : 0);
                uint32_t off = (uint32_t)(crow*40 + col)*2;
                uint32_t r4[4];
                ldm_x4(r4, base + G2_BH*2 + off);
                bh[2*p][0]=r4[0]; bh[2*p][1]=r4[1]; bh[2*p+1][0]=r4[2]; bh[2*p+1][1]=r4[3];
                ldm_x4(r4, base + G2_BL*2 + off);
                bl[2*p][0]=r4[0]; bl[2*p][1]=r4[1]; bl[2*p+1][0]=r4[2]; bl[2*p+1][1]=r4[3];
            }
            #pragma unroll
            for (int mt = 0; mt < 2; mt++)
                #pragma unroll
                for (int ct = 0; ct < 4; ct++) {
                    mma_bf16(acc[mt][ct], ah[mt], bh[ct]);
                    mma_bf16(acc[mt][ct], al[mt], bh[ct]);
                    mma_bf16(acc[mt][ct], ah[mt], bl[ct]);
                }
        }
        __syncthreads();
    }
    int nrow = nt0 + wn + (lane >> 2);
    #pragma unroll
    for (int mt = 0; mt < 2; mt++) {
        #pragma unroll
        for (int ct = 0; ct < 4; ct++) {
            int c0 = ct0 + wc + ct*8 + ((lane & 3) << 1);
            float b0 = g_bias2[b*512 + c0];
            float b1 = g_bias2[b*512 + c0 + 1];
            #pragma unroll
            for (int half = 0; half < 2; half++) {
                int n = nrow + mt*16 + half*8;
                if (n < 3136) {
                    size_t o = ((size_t)b*3136 + n)*512 + c0;
                    *(float2*)&out[o] = make_float2(acc[mt][ct][half*2] + b0,
                                                    acc[mt][ct][half*2+1] + b1);
                }
            }
        }
    }
}

// ---------------- launcher ----------------
extern "C" void kernel_launch(void* const* d_in, const int* in_sizes, int n_in,
                              void* d_out, int out_size) {
    const float* x        = (const float*)d_in[0];
    const float* q_w      = (const float*)d_in[1];
    const float* down_w   = (const float*)d_in[2];
    const float* kv_w     = (const float*)d_in[3];
    const float* proj_w   = (const float*)d_in[4];
    const float* proj_b   = (const float*)d_in[5];
    const float* rel_bias = (const float*)d_in[6];
    const float* expand_w = (const float*)d_in[7];
    const float* gn1_s    = (const float*)d_in[8];
    const float* gn1_b    = (const float*)d_in[9];
    const float* dw_w     = (const float*)d_in[10];
    const float* gn2_s    = (const float*)d_in[11];
    const float* gn2_b    = (const float*)d_in[12];
    const float* reduce_w = (const float*)d_in[13];
    const float* gn3_s    = (const float*)d_in[14];
    const float* gn3_b    = (const float*)d_in[15];
    float* out = (float*)d_out;

    cudaFuncSetAttribute(k_gemm1_fused, cudaFuncAttributeMaxDynamicSharedMemorySize, G1_SMEM);
    cudaFuncSetAttribute(k_gemm2_mma, cudaFuncAttributeMaxDynamicSharedMemorySize, G2_SMEM);
    cudaFuncSetAttribute(k_dw_gn2,    cudaFuncAttributeMaxDynamicSharedMemorySize, B_SMEM);
    cudaFuncSetAttribute(k_dla_out,   cudaFuncAttributeMaxDynamicSharedMemorySize, C_SMEM);

    k_prep<<<33280, 256>>>(x, down_w);
    k_kv  <<<dim3(4, 7, BB), 256>>>(kv_w);
    k_qkvw<<<1152, 256>>>(q_w, proj_w);
    k_gemm1_fused<<<dim3(98, BB), 256, G1_SMEM>>>(rel_bias);
    k_dw_gn2<<<dim3(196, BB), 256, B_SMEM>>>(dw_w, expand_w, gn1_s, gn1_b);
    k_dla_out<<<dim3(392, BB), 256, C_SMEM>>>(dw_w, expand_w, reduce_w, gn2_s, gn2_b);
    k_wvpfin<<<3344, 256>>>(proj_b, gn3_s, gn3_b);
    k_gemm2_mma<<<dim3(8, 25, BB), 256, G2_SMEM>>>(out);
}

// round 15
// speedup vs baseline: 1.0285x; 1.0285x over previous
#include <cuda_runtime.h>
#include <cuda_bf16.h>
#include <math.h>
#include <stdint.h>

#define BB    16
#define CCH   512
#define NN    3136
#define NKK   49
#define HEADS 8
#define JJ    392
#define HIDC  24
#define SCALE 0.125f

// ---------------- device scratch ----------------
__device__ float g_kvx[BB*NKK*CCH];
__device__ float g_kv [BB*NKK*1024];
__device__ float g_Wvp[BB*JJ*CCH];
__device__ __nv_bfloat16 g_xTh[(size_t)BB*NN*CCH];
__device__ __nv_bfloat16 g_xTl[(size_t)BB*NN*CCH];
__device__ __nv_bfloat16 g_wqh[BB*JJ*CCH];
__device__ __nv_bfloat16 g_wvh[BB*CCH*JJ];
__device__ __nv_bfloat16 g_wvl[BB*CCH*JJ];
__device__ float g_attn[(size_t)BB*NN*JJ];
__device__ __nv_bfloat16 g_ath[(size_t)BB*NN*JJ];
__device__ __nv_bfloat16 g_atl[(size_t)BB*NN*JJ];
__device__ float g_part1[BB*98*36];
__device__ float g_part2[BB*3*196*2];
__device__ float g_part3[BB*392*2];
__device__ float g_ab1[BB*HIDC*2];
__device__ float g_ab2[BB*HIDC*2];
__device__ float g_ab3[BB*HEADS*2];
__device__ float g_bias2[BB*CCH];

__device__ __forceinline__ float swishf(float x) { return x / (1.f + __expf(-x)); }

__device__ __forceinline__ void bsplit(float v, __nv_bfloat16& h, __nv_bfloat16& l) {
    h = __float2bfloat16(v);
    l = __float2bfloat16(v - __bfloat162float(h));
}

__device__ __forceinline__ uint32_t smem_u32(const void* p) {
    uint32_t a;
    asm("{ .reg .u64 t; cvta.to.shared.u64 t, %1; cvt.u32.u64 %0, t; }" : "=r"(a) : "l"(p));
    return a;
}
__device__ __forceinline__ void ldm_x4(uint32_t* r, uint32_t addr) {
    asm volatile("ldmatrix.sync.aligned.m8n8.x4.shared.b16 {%0,%1,%2,%3}, [%4];"
        : "=r"(r[0]), "=r"(r[1]), "=r"(r[2]), "=r"(r[3]) : "r"(addr));
}
__device__ __forceinline__ void ldm_x2(uint32_t* r, uint32_t addr) {
    asm volatile("ldmatrix.sync.aligned.m8n8.x2.shared.b16 {%0,%1}, [%2];"
        : "=r"(r[0]), "=r"(r[1]) : "r"(addr));
}
__device__ __forceinline__ void mma_bf16(float* c, const uint32_t* a, const uint32_t* b) {
    asm volatile(
        "mma.sync.aligned.m16n8k16.row.col.f32.bf16.bf16.f32 "
        "{%0,%1,%2,%3}, {%4,%5,%6,%7}, {%8,%9}, {%0,%1,%2,%3};"
        : "+f"(c[0]), "+f"(c[1]), "+f"(c[2]), "+f"(c[3])
        : "r"(a[0]), "r"(a[1]), "r"(a[2]), "r"(a[3]), "r"(b[0]), "r"(b[1]));
}
__device__ __forceinline__ void cpa16(uint32_t dst, const void* src, bool v) {
    int sz = v ? 16 : 0;
    asm volatile("cp.async.cg.shared.global [%0], [%1], 16, %2;"
        :: "r"(dst), "l"(src), "r"(sz) : "memory");
}
__device__ __forceinline__ void cp_commit() {
    asm volatile("cp.async.commit_group;" ::: "memory");
}
__device__ __forceinline__ void cp_wait1() {
    asm volatile("cp.async.wait_group 1;" ::: "memory");
}
__device__ __forceinline__ void cp_wait0() {
    asm volatile("cp.async.wait_group 0;" ::: "memory");
}

// ---------------- 1. k_prep: fused xsplit + down ----------------
__global__ __launch_bounds__(256) void k_prep(const float* __restrict__ x,
                                              const float* __restrict__ down_w) {
    __shared__ float sh[3200];
    int blk = blockIdx.x;
    int t = threadIdx.x;
    if (blk < 25088) {
        int tn = blk % 98;
        int rest = blk / 98;
        int tc = rest & 15, b = rest >> 4;
        float (*tile)[33] = (float(*)[33])sh;
        int a = t >> 5, q = t & 31;
        #pragma unroll
        for (int r = 0; r < 4; r++) {
            int cc = tc*32 + a + r*8, nn = tn*32 + q;
            tile[a + r*8][q] = x[((size_t)b*512 + cc)*3136 + nn];
        }
        __syncthreads();
        #pragma unroll
        for (int r = 0; r < 4; r++) {
            int nn = tn*32 + a + r*8, cc = tc*32 + q;
            float v = tile[q][a + r*8];
            __nv_bfloat16 h, l; bsplit(v, h, l);
            size_t o = ((size_t)b*3136 + nn)*512 + cc;
            g_xTh[o] = h; g_xTl[o] = l;
        }
    } else {
        int bc = blk - 25088, c = bc & 511, b = bc >> 9;
        float* plane = sh;
        float* w = sh + 3136;
        const float* xp = x + (size_t)bc * 3136;
        for (int i = t; i < 3136; i += 256) plane[i] = xp[i];
        if (t < 64) w[t] = down_w[c*64 + t];
        __syncthreads();
        if (t < 49) {
            int my = t / 7, mx = t % 7;
            float s = 0.f;
            #pragma unroll
            for (int i = 0; i < 8; i++)
                #pragma unroll
                for (int j = 0; j < 8; j++)
                    s += plane[(my*8+i)*56 + mx*8 + j] * w[i*8+j];
            g_kvx[(b*49 + t)*512 + c] = s;
        }
    }
}

// ---------------- 2. kv = kvx @ kv_w ----------------
__global__ void k_kv(const float* __restrict__ kv_w) {
    int b = blockIdx.z, m0 = blockIdx.y * 7, oc = blockIdx.x;
    __shared__ float a[7][512];
    for (int i = threadIdx.x; i < 7*512; i += 256)
        a[i >> 9][i & 511] = g_kvx[(b*49 + m0 + (i >> 9))*512 + (i & 511)];
    __syncthreads();
    int o = oc*256 + threadIdx.x;
    float acc[7] = {0,0,0,0,0,0,0};
    for (int c = 0; c < 512; c++) {
        float w = kv_w[c*1024 + o];
        #pragma unroll
        for (int mm = 0; mm < 7; mm++) acc[mm] += a[mm][c] * w;
    }
    #pragma unroll
    for (int mm = 0; mm < 7; mm++)
        g_kv[(b*49 + m0 + mm)*1024 + o] = acc[mm];
}

// ---------------- 3. k_qkvw: fused wqk_split + wvp ----------------
__global__ __launch_bounds__(256) void k_qkvw(const float* __restrict__ q_w,
                                              const float* __restrict__ proj_w) {
    __shared__ float sh[3136];
    int blk = blockIdx.x;
    int t = threadIdx.x;
    if (blk < 256) {
        int half = blk & 1, h = (blk >> 1) & 7, b = blk >> 4;
        float (*ks)[64] = (float(*)[64])sh;
        for (int i = t; i < 49*64; i += 256)
            ks[i >> 6][i & 63] = g_kv[(b*49 + (i >> 6))*1024 + h*64 + (i & 63)];
        __syncthreads();
        int cin = half*256 + t;
        float acc[49];
        #pragma unroll
        for (int m = 0; m < 49; m++) acc[m] = 0.f;
        const float4* q4 = (const float4*)(q_w + (size_t)cin*512 + h*64);
        const float4* ks4 = (const float4*)&ks[0][0];
        for (int d4 = 0; d4 < 16; d4++) {
            float4 q = __ldg(q4 + d4);
            #pragma unroll
            for (int m = 0; m < 49; m++) {
                float4 k = ks4[m*16 + d4];
                acc[m] += q.x*k.x + q.y*k.y + q.z*k.z + q.w*k.w;
            }
        }
        size_t obase = ((size_t)b*392 + h*49)*512 + cin;
        #pragma unroll
        for (int m = 0; m < 49; m++)
            g_wqh[obase + (size_t)m*512] = __float2bfloat16(acc[m] * SCALE);
    } else {
        int q = blk - 256;
        int mc = (q % 7) * 7, h = (q / 7) & 7, b = q / 56;
        float (*vs)[64] = (float(*)[64])sh;
        for (int i = t; i < 7*64; i += 256)
            vs[i >> 6][i & 63] = g_kv[(b*49 + mc + (i >> 6))*1024 + 512 + h*64 + (i & 63)];
        __syncthreads();
        float acc[7][2] = {{0}};
        for (int d = 0; d < 64; d++) {
            float w0 = proj_w[(h*64+d)*512 + t];
            float w1 = proj_w[(h*64+d)*512 + 256 + t];
            #pragma unroll
            for (int mm = 0; mm < 7; mm++) {
                float vv = vs[mm][d];
                acc[mm][0] += vv * w0;
                acc[mm][1] += vv * w1;
            }
        }
        #pragma unroll
        for (int mm = 0; mm < 7; mm++) {
            int j = h*49 + mc + mm;
            g_Wvp[(b*392 + j)*512 + t]       = acc[mm][0];
            g_Wvp[(b*392 + j)*512 + 256 + t] = acc[mm][1];
        }
    }
}

// ---------------- 4. GEMM1 fused (bf16x2; 32n x 416j tiles, k-tile 32, 2 CTAs/SM) ----------------
#define G1_BUFSZ 38400u
#define G1_AHOFF 0u
#define G1_ALOFF 2560u
#define G1_BHOFF 5120u
#define G1_SMEM  76800
__device__ __forceinline__ void g1f_load(uint32_t sb, int b, int nt0, int kt, int p, int t) {
    int k0 = kt*32;
    uint32_t base = sb + (uint32_t)p*G1_BUFSZ;
    {
        int hl = t >= 128;
        int ii = t & 127;
        int row = ii >> 2, q = ii & 3;
        size_t e = ((size_t)b*3136 + nt0 + row)*512 + k0 + q*8;
        uint32_t doff = (uint32_t)(row*40 + q*8)*2;
        cpa16(base + (hl ? G1_ALOFF : G1_AHOFF) + doff, (hl ? g_xTl : g_xTh) + e, true);
    }
    #pragma unroll
    for (int rr = 0; rr < 7; rr++) {
        int idx = rr*256 + t;
        if (idx < 1664) {
            int row = idx >> 2, q = idx & 3;
            bool v = row < 392;
            size_t e = ((size_t)b*392 + (v ? row : 0))*512 + k0 + q*8;
            uint32_t doff = (uint32_t)(row*40 + q*8)*2;
            cpa16(base + G1_BHOFF + doff, g_wqh + e, v);
        }
    }
}

__global__ __launch_bounds__(256, 2) void k_gemm1_fused(const float* __restrict__ rel_bias) {
    extern __shared__ char smraw[];
    uint32_t sb = smem_u32(smraw);
    int b = blockIdx.y, nt0 = blockIdx.x * 32;
    int t = threadIdx.x, w = t >> 5, lane = t & 31;
    int wn = (w & 1)*16, wj = (w >> 1)*104;
    float acc[13][4];
    #pragma unroll
    for (int j = 0; j < 13; j++)
        #pragma unroll
        for (int k = 0; k < 4; k++) acc[j][k] = 0.f;

    g1f_load(sb, b, nt0, 0, 0, t);
    cp_commit();
    for (int kt = 0; kt < 16; kt++) {
        if (kt < 15) {
            g1f_load(sb, b, nt0, kt+1, (kt+1) & 1, t);
            cp_commit();
            cp_wait1();
        } else cp_wait0();
        __syncthreads();
        uint32_t base = sb + (uint32_t)(kt & 1)*G1_BUFSZ;
        #pragma unroll
        for (int kk = 0; kk < 2; kk++) {
            int kb = kk*16;
            uint32_t ah[4], al[4];
            int arow = wn + (lane & 15);
            int acol = kb + ((lane & 16) ? 8 : 0);
            ldm_x4(ah, base + G1_AHOFF + (uint32_t)(arow*40 + acol)*2);
            ldm_x4(al, base + G1_ALOFF + (uint32_t)(arow*40 + acol)*2);
            #pragma unroll
            for (int p2 = 0; p2 < 6; p2++) {
                int jrow = wj + p2*16 + (lane & 7) + ((lane & 16) ? 8 : 0);
                int col = kb + ((lane & 8) ? 8 : 0);
                uint32_t off = (uint32_t)(jrow*40 + col)*2;
                uint32_t rh[4];
                ldm_x4(rh, base + G1_BHOFF + off);
                #pragma unroll
                for (int e = 0; e < 2; e++) {
                    mma_bf16(acc[2*p2+e], ah, &rh[2*e]);
                    mma_bf16(acc[2*p2+e], al, &rh[2*e]);
                }
            }
            {
                int jrow = wj + 96 + (lane & 7);
                int col = kb + ((lane & 8) ? 8 : 0);
                uint32_t off = (uint32_t)(jrow*40 + col)*2;
                uint32_t bh2[2];
                ldm_x2(bh2, base + G1_BHOFF + off);
                mma_bf16(acc[12], ah, bh2);
                mma_bf16(acc[12], al, bh2);
            }
        }
        __syncthreads();
    }
    float* S = (float*)smraw;
    float* Gred = S + 32*400;
    {
        int nl = wn + (lane >> 2);
        #pragma unroll
        for (int jt = 0; jt < 13; jt++) {
            int j0 = wj + jt*8 + ((lane & 3) << 1);
            if (j0 < 392) {
                S[nl*400 + j0]       = acc[jt][0];
                S[nl*400 + j0 + 1]   = acc[jt][1];
                S[(nl+8)*400 + j0]   = acc[jt][2];
                S[(nl+8)*400 + j0+1] = acc[jt][3];
            }
        }
    }
    __syncthreads();
    {
        int n = t >> 3, h = t & 7;
        float* p = S + n*400 + h*49;
        const float* rb = rel_bias + (size_t)(nt0 + n)*49;
        float mx = -1e30f;
        for (int i = 0; i < 49; i++) {
            float lv = p[i] + __ldg(rb + i);
            p[i] = lv;
            mx = fmaxf(mx, lv);
        }
        float sum = 0.f;
        for (int i = 0; i < 49; i++) { float e = __expf(p[i] - mx); p[i] = e; sum += e; }
        float inv = 1.f / sum;
        for (int i = 0; i < 49; i++) p[i] *= inv;
    }
    __syncthreads();
    float g[36];
    #pragma unroll
    for (int k = 0; k < 36; k++) g[k] = 0.f;
    for (int pos = t; pos < 32*49; pos += 256) {
        int n = pos / 49, m = pos - n*49;
        float a[8];
        #pragma unroll
        for (int h = 0; h < 8; h++) a[h] = S[n*400 + h*49 + m];
        int k = 0;
        #pragma unroll
        for (int h = 0; h < 8; h++)
            #pragma unroll
            for (int h2 = h; h2 < 8; h2++) { g[k] += a[h]*a[h2]; k++; }
    }
    size_t ob = ((size_t)b*3136 + nt0)*392;
    for (int i = t; i < 32*392; i += 256) {
        int n = i / 392, c = i - n*392;
        g_attn[ob + i] = S[n*400 + c];
    }
    #pragma unroll
    for (int s = 16; s; s >>= 1)
        #pragma unroll
        for (int k = 0; k < 36; k++) g[k] += __shfl_xor_sync(0xffffffffu, g[k], s);
    if (lane == 0)
        #pragma unroll
        for (int k = 0; k < 36; k++) Gred[w*36 + k] = g[k];
    __syncthreads();
    if (t < 36) {
        float s = 0.f;
        #pragma unroll
        for (int ww = 0; ww < 8; ww++) s += Gred[ww*36 + t];
        g_part1[((size_t)b*98 + blockIdx.x)*36 + t] = s;
    }
}

// ---------------- 5. gn1 finalize from Gram ----------------
__global__ void k_gn1_final(const float* __restrict__ gs, const float* __restrict__ gb,
                            const float* __restrict__ ew) {
    int b = blockIdx.x, t = threadIdx.x;   // 64 threads
    __shared__ float M36[36];
    __shared__ float Mf[64];
    __shared__ float s1s[24], sqs[24];
    __shared__ float mg[3], rg[3];
    if (t < 36) {
        float s = 0.f;
        for (int nt = 0; nt < 98; nt++) s += g_part1[((size_t)b*98 + nt)*36 + t];
        M36[t] = s;
    }
    __syncthreads();
    if (t == 0) {
        int k = 0;
        for (int h = 0; h < 8; h++)
            for (int h2 = h; h2 < 8; h2++) { Mf[h*8+h2] = M36[k]; Mf[h2*8+h] = M36[k]; k++; }
    }
    __syncthreads();
    if (t < 24) {
        float wv[8], sw = 0.f;
        #pragma unroll
        for (int h = 0; h < 8; h++) { wv[h] = ew[t*8+h]; sw += wv[h]; }
        float sq = 0.f;
        #pragma unroll
        for (int h = 0; h < 8; h++)
            #pragma unroll
            for (int h2 = 0; h2 < 8; h2++) sq += wv[h]*wv[h2]*Mf[h*8+h2];
        s1s[t] = 3136.f * sw;
        sqs[t] = sq;
    }
    __syncthreads();
    if (t < 3) {
        float s1 = 0.f, sq = 0.f;
        for (int c = 0; c < 8; c++) { s1 += s1s[t*8+c]; sq += sqs[t*8+c]; }
        float cnt = 8.f*3136.f*49.f;
        float mean = s1/cnt;
        float var  = sq/cnt - mean*mean;
        mg[t] = mean;
        rg[t] = rsqrtf(var + 1e-5f);
    }
    __syncthreads();
    if (t < 24) {
        float A = rg[t>>3]*gs[t];
        g_ab1[(b*24 + t)*2]     = A;
        g_ab1[(b*24 + t)*2 + 1] = gb[t] - mg[t>>3]*A;
    }
}

// ---------------- stats finalize (gn2/gn3) ----------------
__global__ void k_stats_final(const float* __restrict__ gs, const float* __restrict__ gb,
                              float* __restrict__ ab, const float* __restrict__ part,
                              int G, int npart) {
    int b = blockIdx.x / G, g = blockIdx.x % G;
    const float* p = part + (size_t)(b*G + g)*npart*2;
    float sm = 0.f, sq = 0.f;
    for (int i = threadIdx.x; i < npart; i += 256) { sm += p[2*i]; sq += p[2*i+1]; }
    __shared__ float rs[256], rq[256];
    __shared__ float mean_s, rstd_s;
    int t = threadIdx.x;
    rs[t] = sm; rq[t] = sq;
    __syncthreads();
    for (int st = 128; st; st >>= 1) {
        if (t < st) { rs[t] += rs[t+st]; rq[t] += rq[t+st]; }
        __syncthreads();
    }
    if (!t) {
        float cnt  = 8.f * 3136.f * 49.f;
        float mean = rs[0] / cnt;
        float var  = rq[0] / cnt - mean*mean;
        mean_s = mean;
        rstd_s = rsqrtf(var + 1e-5f);
    }
    __syncthreads();
    if (t < 8) {
        int c = g*8 + t;
        float A = rstd_s * gs[c];
        int CH = G*8;
        ab[(b*CH + c)*2]     = A;
        ab[(b*CH + c)*2 + 1] = gb[c] - mean_s*A;
    }
}

// ---------------- 6. pass B: warp-parallel expand+dw -> gn2 partials ----------------
#define B_AT  0
#define B_HID 7056
#define B_EW  14416
#define B_AB  14608
#define B_RED 14656
#define B_TOT (14656 + 1536)
#define B_SMEM (B_TOT*4)
__global__ __launch_bounds__(256) void k_dw_gn2(const float* __restrict__ dw_w,
                                                const float* __restrict__ expand_w) {
    extern __shared__ float sm[];
    float* at  = sm + B_AT;
    float* ew  = sm + B_EW;
    float* ab  = sm + B_AB;
    float* red = sm + B_RED;
    int nt = blockIdx.x, b = blockIdx.y, t = threadIdx.x;
    int w = t >> 5, lane = t & 31;
    float* hid = sm + B_HID + w*920;
    int n0 = nt * 16;
    if (t < 192) ew[t] = expand_w[t];
    if (t >= 192 && t < 240) ab[t-192] = g_ab1[b*48 + (t-192)];
    for (int i = t; i < 18*392; i += 256) {
        int r = i / 392, m = i - r*392;
        int n = n0 - 1 + r;
        at[i] = (n >= 0 && n < 3136) ? g_attn[((size_t)b*3136 + n)*392 + m] : 0.f;
    }
    __syncthreads();
    float sk[3] = {0,0,0}, qk[3] = {0,0,0};
    #pragma unroll
    for (int k = 0; k < 3; k++) {
        int c = w + k*8;
        float A1 = ab[c*2], B1 = ab[c*2+1];
        const float* wp = ew + c*8;
        for (int i = lane; i < 918; i += 32) {
            int r = i / 51, mm = i - r*51;
            int n = n0 - 1 + r;
            float v = 0.f;
            if (mm >= 1 && mm <= 49 && n >= 0 && n < 3136) {
                const float* sp = at + r*392 + (mm - 1);
                float hsum = 0.f;
                #pragma unroll
                for (int hh = 0; hh < 8; hh++) hsum += sp[hh*49] * wp[hh];
                v = swishf(A1*hsum + B1);
            }
            hid[i] = v;
        }
        __syncwarp();
        float lw[9];
        #pragma unroll
        for (int i = 0; i < 9; i++) lw[i] = dw_w[c*9 + i];
        for (int o = lane; o < 784; o += 32) {
            int ny = o / 49, m = o - ny*49;
            float a = 0.f;
            #pragma unroll
            for (int dy = 0; dy < 3; dy++)
                #pragma unroll
                for (int dx = 0; dx < 3; dx++)
                    a += hid[(ny+dy)*51 + m+dx] * lw[dy*3+dx];
            sk[k] += a; qk[k] += a*a;
        }
        __syncwarp();
    }
    #pragma unroll
    for (int g = 0; g < 3; g++) { red[g*256 + t] = sk[g]; red[(3+g)*256 + t] = qk[g]; }
    __syncthreads();
    for (int st = 128; st; st >>= 1) {
        if (t < st)
            #pragma unroll
            for (int g = 0; g < 6; g++) red[g*256 + t] += red[g*256 + t + st];
        __syncthreads();
    }
    if (t < 3) {
        g_part2[((b*3 + t)*196 + nt)*2]     = red[t*256];
        g_part2[((b*3 + t)*196 + nt)*2 + 1] = red[(t+3)*256];
    }
}

// ---------------- 7. pass C: expand+dw+norm2+swish, reduce -> attnF + gn3 ----------------
#define C_AT  0
#define C_HID 3920
#define C_DWS 8016
#define C_EW  17424
#define C_RW  17616
#define C_AB  17808
#define C_RED 17904
#define C_TOT (17904 + 512)
#define C_SMEM (C_TOT*4)
__global__ __launch_bounds__(256) void k_dla_out(const float* __restrict__ dw_w,
                                                 const float* __restrict__ expand_w,
                                                 const float* __restrict__ reduce_w) {
    extern __shared__ float sm[];
    float* at  = sm + C_AT;
    float* dws = sm + C_DWS;
    float* ew  = sm + C_EW;
    float* rw  = sm + C_RW;
    float* ab  = sm + C_AB;
    float* red = sm + C_RED;
    int nt = blockIdx.x, b = blockIdx.y, t = threadIdx.x;
    int w = t >> 5, lane = t & 31;
    float* hid = sm + C_HID + w*512;
    int n0 = nt * 8;
    if (t < 192) { ew[t] = expand_w[t]; rw[t] = reduce_w[t]; }
    if (t < 96) ab[t] = (t < 48) ? g_ab1[b*48 + t] : g_ab2[b*48 + (t-48)];
    for (int i = t; i < 10*392; i += 256) {
        int r = i / 392, m = i - r*392;
        int n = n0 - 1 + r;
        at[i] = (n >= 0 && n < 3136) ? g_attn[((size_t)b*3136 + n)*392 + m] : 0.f;
    }
    __syncthreads();
    #pragma unroll
    for (int k = 0; k < 3; k++) {
        int c = w + k*8;
        float A1 = ab[c*2], B1 = ab[c*2+1];
        float A2 = ab[48 + c*2], B2 = ab[49 + c*2];
        const float* wp = ew + c*8;
        for (int i = lane; i < 510; i += 32) {
            int r = i / 51, mm = i - r*51;
            int n = n0 - 1 + r;
            float v = 0.f;
            if (mm >= 1 && mm <= 49 && n >= 0 && n < 3136) {
                const float* sp = at + r*392 + (mm - 1);
                float hsum = 0.f;
                #pragma unroll
                for (int hh = 0; hh < 8; hh++) hsum += sp[hh*49] * wp[hh];
                v = swishf(A1*hsum + B1);
            }
            hid[i] = v;
        }
        __syncwarp();
        float lw[9];
        #pragma unroll
        for (int i = 0; i < 9; i++) lw[i] = dw_w[c*9 + i];
        for (int o = lane; o < 392; o += 32) {
            int ny = o / 49, m = o - ny*49;
            float a = 0.f;
            #pragma unroll
            for (int dy = 0; dy < 3; dy++)
                #pragma unroll
                for (int dx = 0; dx < 3; dx++)
                    a += hid[(ny+dy)*51 + m+dx] * lw[dy*3+dx];
            dws[(ny*24 + c)*49 + m] = swishf(A2*a + B2);
        }
        __syncwarp();
    }
    __syncthreads();
    float lsum = 0.f, lsq = 0.f;
    for (int o = t; o < 392; o += 256) {
        int ny = o / 49, m = o - ny*49;
        int n = n0 + ny;
        float in[24];
        #pragma unroll
        for (int c = 0; c < 24; c++) in[c] = dws[(ny*24 + c)*49 + m];
        size_t ob = ((size_t)b*3136 + n)*392 + m;
        #pragma unroll
        for (int h = 0; h < 8; h++) {
            float r = 0.f;
            #pragma unroll
            for (int c = 0; c < 24; c++) r += in[c] * rw[h*24 + c];
            __nv_bfloat16 hh, ll; bsplit(r, hh, ll);
            g_ath[ob + h*49] = hh;
            g_atl[ob + h*49] = ll;
            lsum += r; lsq += r*r;
        }
    }
    red[t] = lsum; red[256 + t] = lsq;
    __syncthreads();
    for (int st = 128; st; st >>= 1) {
        if (t < st) { red[t] += red[t+st]; red[256+t] += red[256+t+st]; }
        __syncthreads();
    }
    if (!t) {
        g_part3[(b*392 + nt)*2]     = red[0];
        g_part3[(b*392 + nt)*2 + 1] = red[256];
    }
}

// ---------------- 8. k_wvpfin: fused wvpsplit (blocks 0..3327) + wvpbias (3328..3343) ----------------
__global__ __launch_bounds__(256) void k_wvpfin(const float* __restrict__ proj_b) {
    __shared__ float tile[32][33];
    int blk = blockIdx.x;
    int t = threadIdx.x;
    if (blk < 3328) {
        int tj = blk % 13;
        int rest = blk / 13;
        int tc = rest & 15, b = rest >> 4;
        int a = t >> 5, q = t & 31;
        #pragma unroll
        for (int r = 0; r < 4; r++) {
            int jj = tj*32 + a + r*8, cc = tc*32 + q;
            float v = 0.f;
            if (jj < 392) v = g_Wvp[((size_t)b*392 + jj)*512 + cc] * g_ab3[(b*8 + jj/49)*2];
            tile[a + r*8][q] = v;
        }
        __syncthreads();
        #pragma unroll
        for (int r = 0; r < 4; r++) {
            int cc = tc*32 + a + r*8, jj = tj*32 + q;
            if (jj < 392) {
                float v = tile[q][a + r*8];
                __nv_bfloat16 h, l; bsplit(v, h, l);
                size_t o = ((size_t)b*512 + cc)*392 + jj;
                g_wvh[o] = h; g_wvl[o] = l;
            }
        }
    } else {
        int b = blk - 3328;
        #pragma unroll
        for (int cc = 0; cc < 2; cc++) {
            int c = t + cc*256;
            float acc = 0.f;
            for (int j = 0; j < 392; j++)
                acc += g_ab3[(b*8 + j/49)*2 + 1] * g_Wvp[((size_t)b*392 + j)*512 + c];
            g_bias2[b*512 + c] = acc + proj_b[c];
        }
    }
}

// ---------------- 9. GEMM2 (bf16x3 mma.sync, forced 2 CTAs/SM) ----------------
#define G2_BUF 15360
#define G2_AH 0
#define G2_AL 5120
#define G2_BH 10240
#define G2_BL 12800
#define G2_SMEM (G2_BUF*2*2)
__device__ __forceinline__ void g2_load(uint32_t sb, int b, int nt0, int ct0,
                                        int kt, int p, int t) {
    int k0 = kt*32;
    uint32_t base = sb + (uint32_t)p*G2_BUF*2;
    #pragma unroll
    for (int rr = 0; rr < 2; rr++) {
        int idx = t + rr*256;
        int row = idx >> 2, q = idx & 3;
        int n = nt0 + row, j0 = k0 + q*8;
        bool v = (n < 3136) && (j0 < 392);
        size_t e = ((size_t)b*3136 + (n < 3136 ? n : 0))*392 + (j0 < 392 ? j0 : 0);
        uint32_t doff = (uint32_t)(row*40 + q*8)*2;
        cpa16(base + G2_AH*2 + doff, g_ath + e, v);
        cpa16(base + G2_AL*2 + doff, g_atl + e, v);
    }
    {
        int idx = t;
        int row = idx >> 2, q = idx & 3;
        int c = ct0 + row, j0 = k0 + q*8;
        bool v = j0 < 392;
        size_t e = ((size_t)b*512 + c)*392 + (v ? j0 : 0);
        uint32_t doff = (uint32_t)(row*40 + q*8)*2;
        cpa16(base + G2_BH*2 + doff, g_wvh + e, v);
        cpa16(base + G2_BL*2 + doff, g_wvl + e, v);
    }
}

__global__ __launch_bounds__(256, 2) void k_gemm2_mma(float* __restrict__ out) {
    extern __shared__ __nv_bfloat16 dsm2[];
    uint32_t sb = smem_u32(dsm2);
    int b = blockIdx.z, nt0 = blockIdx.y*128, ct0 = blockIdx.x*64;
    int t = threadIdx.x, w = t >> 5, lane = t & 31;
    int wn = (w & 3)*32, wc = (w >> 2)*32;
    float acc[2][4][4];
    #pragma unroll
    for (int i = 0; i < 2; i++)
        #pragma unroll
        for (int j = 0; j < 4; j++)
            #pragma unroll
            for (int k = 0; k < 4; k++) acc[i][j][k] = 0.f;

    g2_load(sb, b, nt0, ct0, 0, 0, t);
    cp_commit();
    for (int kt = 0; kt < 13; kt++) {
        if (kt < 12) {
            g2_load(sb, b, nt0, ct0, kt+1, (kt+1) & 1, t);
            cp_commit();
            cp_wait1();
        } else cp_wait0();
        __syncthreads();
        uint32_t base = sb + (uint32_t)(kt & 1)*G2_BUF*2;
        #pragma unroll
        for (int kk = 0; kk < 2; kk++) {
            int kb = kk*16;
            uint32_t ah[2][4], al[2][4];
            #pragma unroll
            for (int mt = 0; mt < 2; mt++) {
                int row = wn + mt*16 + (lane & 15);
                int col = kb + ((lane & 16) ? 8 : 0);
                uint32_t off = (uint32_t)(row*40 + col)*2;
                ldm_x4(ah[mt], base + G2_AH*2 + off);
                ldm_x4(al[mt], base + G2_AL*2 + off);
            }
            uint32_t bh[4][2], bl[4][2];
            #pragma unroll
            for (int p = 0; p < 2; p++) {
                int crow = wc + p*16 + (lane & 7) + ((lane & 16) ? 8 : 0);
                int col = kb + ((lane & 8) ? 8 : 0);
                uint32_t off = (uint32_t)(crow*40 + col)*2;
                uint32_t r4[4];
                ldm_x4(r4, base + G2_BH*2 + off);
                bh[2*p][0]=r4[0]; bh[2*p][1]=r4[1]; bh[2*p+1][0]=r4[2]; bh[2*p+1][1]=r4[3];
                ldm_x4(r4, base + G2_BL*2 + off);
                bl[2*p][0]=r4[0]; bl[2*p][1]=r4[1]; bl[2*p+1][0]=r4[2]; bl[2*p+1][1]=r4[3];
            }
            #pragma unroll
            for (int mt = 0; mt < 2; mt++)
                #pragma unroll
                for (int ct = 0; ct < 4; ct++) {
                    mma_bf16(acc[mt][ct], ah[mt], bh[ct]);
                    mma_bf16(acc[mt][ct], al[mt], bh[ct]);
                    mma_bf16(acc[mt][ct], ah[mt], bl[ct]);
                }
        }
        __syncthreads();
    }
    int nrow = nt0 + wn + (lane >> 2);
    #pragma unroll
    for (int mt = 0; mt < 2; mt++) {
        #pragma unroll
        for (int ct = 0; ct < 4; ct++) {
            int c0 = ct0 + wc + ct*8 + ((lane & 3) << 1);
            float b0 = g_bias2[b*512 + c0];
            float b1 = g_bias2[b*512 + c0 + 1];
            #pragma unroll
            for (int half = 0; half < 2; half++) {
                int n = nrow + mt*16 + half*8;
                if (n < 3136) {
                    size_t o = ((size_t)b*3136 + n)*512 + c0;
                    *(float2*)&out[o] = make_float2(acc[mt][ct][half*2] + b0,
                                                    acc[mt][ct][half*2+1] + b1);
                }
            }
        }
    }
}

// ---------------- launcher ----------------
extern "C" void kernel_launch(void* const* d_in, const int* in_sizes, int n_in,
                              void* d_out, int out_size) {
    const float* x        = (const float*)d_in[0];
    const float* q_w      = (const float*)d_in[1];
    const float* down_w   = (const float*)d_in[2];
    const float* kv_w     = (const float*)d_in[3];
    const float* proj_w   = (const float*)d_in[4];
    const float* proj_b   = (const float*)d_in[5];
    const float* rel_bias = (const float*)d_in[6];
    const float* expand_w = (const float*)d_in[7];
    const float* gn1_s    = (const float*)d_in[8];
    const float* gn1_b    = (const float*)d_in[9];
    const float* dw_w     = (const float*)d_in[10];
    const float* gn2_s    = (const float*)d_in[11];
    const float* gn2_b    = (const float*)d_in[12];
    const float* reduce_w = (const float*)d_in[13];
    const float* gn3_s    = (const float*)d_in[14];
    const float* gn3_b    = (const float*)d_in[15];
    float* out = (float*)d_out;

    float *ab2, *ab3, *p2, *p3;
    cudaGetSymbolAddress((void**)&ab2, g_ab2);
    cudaGetSymbolAddress((void**)&ab3, g_ab3);
    cudaGetSymbolAddress((void**)&p2, g_part2);
    cudaGetSymbolAddress((void**)&p3, g_part3);

    cudaFuncSetAttribute(k_gemm1_fused, cudaFuncAttributeMaxDynamicSharedMemorySize, G1_SMEM);
    cudaFuncSetAttribute(k_gemm2_mma, cudaFuncAttributeMaxDynamicSharedMemorySize, G2_SMEM);
    cudaFuncSetAttribute(k_dw_gn2,    cudaFuncAttributeMaxDynamicSharedMemorySize, B_SMEM);
    cudaFuncSetAttribute(k_dla_out,   cudaFuncAttributeMaxDynamicSharedMemorySize, C_SMEM);

    k_prep<<<33280, 256>>>(x, down_w);
    k_kv  <<<dim3(4, 7, BB), 256>>>(kv_w);
    k_qkvw<<<1152, 256>>>(q_w, proj_w);
    k_gemm1_fused<<<dim3(98, BB), 256, G1_SMEM>>>(rel_bias);
    k_gn1_final<<<BB, 64>>>(gn1_s, gn1_b, expand_w);
    k_dw_gn2<<<dim3(196, BB), 256, B_SMEM>>>(dw_w, expand_w);
    k_stats_final<<<BB*3, 256>>>(gn2_s, gn2_b, ab2, p2, 3, 196);
    k_dla_out<<<dim3(392, BB), 256, C_SMEM>>>(dw_w, expand_w, reduce_w);
    k_stats_final<<<BB, 256>>>(gn3_s, gn3_b, ab3, p3, 1, 392);
    k_wvpfin<<<3344, 256>>>(proj_b);
    k_gemm2_mma<<<dim3(8, 25, BB), 256, G2_SMEM>>>(out);
}

// round 16
// speedup vs baseline: 1.0618x; 1.0324x over previous
#include <cuda_runtime.h>
#include <cuda_bf16.h>
#include <math.h>
#include <stdint.h>

#define BB    16
#define CCH   512
#define NN    3136
#define NKK   49
#define HEADS 8
#define JJ    392
#define HIDC  24
#define SCALE 0.125f

// ---------------- device scratch ----------------
__device__ float g_kvx[BB*NKK*CCH];
__device__ float g_kv [BB*NKK*1024];
__device__ float g_Wvp[BB*JJ*CCH];
__device__ __nv_bfloat16 g_xTh[(size_t)BB*NN*CCH];
__device__ __nv_bfloat16 g_xTl[(size_t)BB*NN*CCH];
__device__ __nv_bfloat16 g_wqh[BB*JJ*CCH];
__device__ __nv_bfloat16 g_wvh[BB*CCH*JJ];
__device__ __nv_bfloat16 g_wvl[BB*CCH*JJ];
__device__ float g_attn[(size_t)BB*NN*JJ];
__device__ __nv_bfloat16 g_ath[(size_t)BB*NN*JJ];
__device__ __nv_bfloat16 g_atl[(size_t)BB*NN*JJ];
__device__ float g_part1[BB*98*36];
__device__ float g_part2[BB*3*196*2];
__device__ float g_part3[BB*392*2];
__device__ float g_ab1[BB*HIDC*2];
__device__ float g_ab2[BB*HIDC*2];
__device__ float g_ab3[BB*HEADS*2];
__device__ float g_bias2[BB*CCH];

__device__ __forceinline__ float swishf(float x) { return x / (1.f + __expf(-x)); }

__device__ __forceinline__ void bsplit(float v, __nv_bfloat16& h, __nv_bfloat16& l) {
    h = __float2bfloat16(v);
    l = __float2bfloat16(v - __bfloat162float(h));
}

__device__ __forceinline__ uint32_t smem_u32(const void* p) {
    uint32_t a;
    asm("{ .reg .u64 t; cvta.to.shared.u64 t, %1; cvt.u32.u64 %0, t; }" : "=r"(a) : "l"(p));
    return a;
}
__device__ __forceinline__ void ldm_x4(uint32_t* r, uint32_t addr) {
    asm volatile("ldmatrix.sync.aligned.m8n8.x4.shared.b16 {%0,%1,%2,%3}, [%4];"
        : "=r"(r[0]), "=r"(r[1]), "=r"(r[2]), "=r"(r[3]) : "r"(addr));
}
__device__ __forceinline__ void ldm_x2(uint32_t* r, uint32_t addr) {
    asm volatile("ldmatrix.sync.aligned.m8n8.x2.shared.b16 {%0,%1}, [%2];"
        : "=r"(r[0]), "=r"(r[1]) : "r"(addr));
}
__device__ __forceinline__ void mma_bf16(float* c, const uint32_t* a, const uint32_t* b) {
    asm volatile(
        "mma.sync.aligned.m16n8k16.row.col.f32.bf16.bf16.f32 "
        "{%0,%1,%2,%3}, {%4,%5,%6,%7}, {%8,%9}, {%0,%1,%2,%3};"
        : "+f"(c[0]), "+f"(c[1]), "+f"(c[2]), "+f"(c[3])
        : "r"(a[0]), "r"(a[1]), "r"(a[2]), "r"(a[3]), "r"(b[0]), "r"(b[1]));
}
__device__ __forceinline__ void cpa16(uint32_t dst, const void* src, bool v) {
    int sz = v ? 16 : 0;
    asm volatile("cp.async.cg.shared.global [%0], [%1], 16, %2;"
        :: "r"(dst), "l"(src), "r"(sz) : "memory");
}
__device__ __forceinline__ void cp_commit() {
    asm volatile("cp.async.commit_group;" ::: "memory");
}
__device__ __forceinline__ void cp_wait1() {
    asm volatile("cp.async.wait_group 1;" ::: "memory");
}
__device__ __forceinline__ void cp_wait0() {
    asm volatile("cp.async.wait_group 0;" ::: "memory");
}

// ---------------- 1. k_prep: fused xsplit + down ----------------
__global__ __launch_bounds__(256) void k_prep(const float* __restrict__ x,
                                              const float* __restrict__ down_w) {
    __shared__ float sh[3200];
    int blk = blockIdx.x;
    int t = threadIdx.x;
    if (blk < 25088) {
        int tn = blk % 98;
        int rest = blk / 98;
        int tc = rest & 15, b = rest >> 4;
        float (*tile)[33] = (float(*)[33])sh;
        int a = t >> 5, q = t & 31;
        #pragma unroll
        for (int r = 0; r < 4; r++) {
            int cc = tc*32 + a + r*8, nn = tn*32 + q;
            tile[a + r*8][q] = x[((size_t)b*512 + cc)*3136 + nn];
        }
        __syncthreads();
        #pragma unroll
        for (int r = 0; r < 4; r++) {
            int nn = tn*32 + a + r*8, cc = tc*32 + q;
            float v = tile[q][a + r*8];
            __nv_bfloat16 h, l; bsplit(v, h, l);
            size_t o = ((size_t)b*3136 + nn)*512 + cc;
            g_xTh[o] = h; g_xTl[o] = l;
        }
    } else {
        int bc = blk - 25088, c = bc & 511, b = bc >> 9;
        float* plane = sh;
        float* w = sh + 3136;
        const float* xp = x + (size_t)bc * 3136;
        for (int i = t; i < 3136; i += 256) plane[i] = xp[i];
        if (t < 64) w[t] = down_w[c*64 + t];
        __syncthreads();
        if (t < 49) {
            int my = t / 7, mx = t % 7;
            float s = 0.f;
            #pragma unroll
            for (int i = 0; i < 8; i++)
                #pragma unroll
                for (int j = 0; j < 8; j++)
                    s += plane[(my*8+i)*56 + mx*8 + j] * w[i*8+j];
            g_kvx[(b*49 + t)*512 + c] = s;
        }
    }
}

// ---------------- 2. kv = kvx @ kv_w ----------------
__global__ void k_kv(const float* __restrict__ kv_w) {
    int b = blockIdx.z, m0 = blockIdx.y * 7, oc = blockIdx.x;
    __shared__ float a[7][512];
    for (int i = threadIdx.x; i < 7*512; i += 256)
        a[i >> 9][i & 511] = g_kvx[(b*49 + m0 + (i >> 9))*512 + (i & 511)];
    __syncthreads();
    int o = oc*256 + threadIdx.x;
    float acc[7] = {0,0,0,0,0,0,0};
    for (int c = 0; c < 512; c++) {
        float w = kv_w[c*1024 + o];
        #pragma unroll
        for (int mm = 0; mm < 7; mm++) acc[mm] += a[mm][c] * w;
    }
    #pragma unroll
    for (int mm = 0; mm < 7; mm++)
        g_kv[(b*49 + m0 + mm)*1024 + o] = acc[mm];
}

// ---------------- 3. k_qkvw: fused wqk_split + wvp ----------------
__global__ __launch_bounds__(256) void k_qkvw(const float* __restrict__ q_w,
                                              const float* __restrict__ proj_w) {
    __shared__ float sh[3136];
    int blk = blockIdx.x;
    int t = threadIdx.x;
    if (blk < 256) {
        int half = blk & 1, h = (blk >> 1) & 7, b = blk >> 4;
        float (*ks)[64] = (float(*)[64])sh;
        for (int i = t; i < 49*64; i += 256)
            ks[i >> 6][i & 63] = g_kv[(b*49 + (i >> 6))*1024 + h*64 + (i & 63)];
        __syncthreads();
        int cin = half*256 + t;
        float acc[49];
        #pragma unroll
        for (int m = 0; m < 49; m++) acc[m] = 0.f;
        const float4* q4 = (const float4*)(q_w + (size_t)cin*512 + h*64);
        const float4* ks4 = (const float4*)&ks[0][0];
        for (int d4 = 0; d4 < 16; d4++) {
            float4 q = __ldg(q4 + d4);
            #pragma unroll
            for (int m = 0; m < 49; m++) {
                float4 k = ks4[m*16 + d4];
                acc[m] += q.x*k.x + q.y*k.y + q.z*k.z + q.w*k.w;
            }
        }
        size_t obase = ((size_t)b*392 + h*49)*512 + cin;
        #pragma unroll
        for (int m = 0; m < 49; m++)
            g_wqh[obase + (size_t)m*512] = __float2bfloat16(acc[m] * SCALE);
    } else {
        int q = blk - 256;
        int mc = (q % 7) * 7, h = (q / 7) & 7, b = q / 56;
        float (*vs)[64] = (float(*)[64])sh;
        for (int i = t; i < 7*64; i += 256)
            vs[i >> 6][i & 63] = g_kv[(b*49 + mc + (i >> 6))*1024 + 512 + h*64 + (i & 63)];
        __syncthreads();
        float acc[7][2] = {{0}};
        for (int d = 0; d < 64; d++) {
            float w0 = proj_w[(h*64+d)*512 + t];
            float w1 = proj_w[(h*64+d)*512 + 256 + t];
            #pragma unroll
            for (int mm = 0; mm < 7; mm++) {
                float vv = vs[mm][d];
                acc[mm][0] += vv * w0;
                acc[mm][1] += vv * w1;
            }
        }
        #pragma unroll
        for (int mm = 0; mm < 7; mm++) {
            int j = h*49 + mc + mm;
            g_Wvp[(b*392 + j)*512 + t]       = acc[mm][0];
            g_Wvp[(b*392 + j)*512 + 256 + t] = acc[mm][1];
        }
    }
}

// ---------------- 4. GEMM1 fused (bf16x2; 32n x 416j tiles, k-tile 32, 2 CTAs/SM) ----------------
#define G1_BUFSZ 38400u
#define G1_AHOFF 0u
#define G1_ALOFF 2560u
#define G1_BHOFF 5120u
#define G1_SMEM  76800
__device__ __forceinline__ void g1f_load(uint32_t sb, int b, int nt0, int kt, int p, int t) {
    int k0 = kt*32;
    uint32_t base = sb + (uint32_t)p*G1_BUFSZ;
    {
        int hl = t >= 128;
        int ii = t & 127;
        int row = ii >> 2, q = ii & 3;
        size_t e = ((size_t)b*3136 + nt0 + row)*512 + k0 + q*8;
        uint32_t doff = (uint32_t)(row*40 + q*8)*2;
        cpa16(base + (hl ? G1_ALOFF : G1_AHOFF) + doff, (hl ? g_xTl : g_xTh) + e, true);
    }
    #pragma unroll
    for (int rr = 0; rr < 7; rr++) {
        int idx = rr*256 + t;
        if (idx < 1664) {
            int row = idx >> 2, q = idx & 3;
            bool v = row < 392;
            size_t e = ((size_t)b*392 + (v ? row : 0))*512 + k0 + q*8;
            uint32_t doff = (uint32_t)(row*40 + q*8)*2;
            cpa16(base + G1_BHOFF + doff, g_wqh + e, v);
        }
    }
}

__global__ __launch_bounds__(256, 2) void k_gemm1_fused(const float* __restrict__ rel_bias) {
    extern __shared__ char smraw[];
    uint32_t sb = smem_u32(smraw);
    int b = blockIdx.y, nt0 = blockIdx.x * 32;
    int t = threadIdx.x, w = t >> 5, lane = t & 31;
    int wn = (w & 1)*16, wj = (w >> 1)*104;
    float acc[13][4];
    #pragma unroll
    for (int j = 0; j < 13; j++)
        #pragma unroll
        for (int k = 0; k < 4; k++) acc[j][k] = 0.f;

    g1f_load(sb, b, nt0, 0, 0, t);
    cp_commit();
    for (int kt = 0; kt < 16; kt++) {
        if (kt < 15) {
            g1f_load(sb, b, nt0, kt+1, (kt+1) & 1, t);
            cp_commit();
            cp_wait1();
        } else cp_wait0();
        __syncthreads();
        uint32_t base = sb + (uint32_t)(kt & 1)*G1_BUFSZ;
        #pragma unroll
        for (int kk = 0; kk < 2; kk++) {
            int kb = kk*16;
            uint32_t ah[4], al[4];
            int arow = wn + (lane & 15);
            int acol = kb + ((lane & 16) ? 8 : 0);
            ldm_x4(ah, base + G1_AHOFF + (uint32_t)(arow*40 + acol)*2);
            ldm_x4(al, base + G1_ALOFF + (uint32_t)(arow*40 + acol)*2);
            #pragma unroll
            for (int p2 = 0; p2 < 6; p2++) {
                int jrow = wj + p2*16 + (lane & 7) + ((lane & 16) ? 8 : 0);
                int col = kb + ((lane & 8) ? 8 : 0);
                uint32_t off = (uint32_t)(jrow*40 + col)*2;
                uint32_t rh[4];
                ldm_x4(rh, base + G1_BHOFF + off);
                #pragma unroll
                for (int e = 0; e < 2; e++) {
                    mma_bf16(acc[2*p2+e], ah, &rh[2*e]);
                    mma_bf16(acc[2*p2+e], al, &rh[2*e]);
                }
            }
            {
                int jrow = wj + 96 + (lane & 7);
                int col = kb + ((lane & 8) ? 8 : 0);
                uint32_t off = (uint32_t)(jrow*40 + col)*2;
                uint32_t bh2[2];
                ldm_x2(bh2, base + G1_BHOFF + off);
                mma_bf16(acc[12], ah, bh2);
                mma_bf16(acc[12], al, bh2);
            }
        }
        __syncthreads();
    }
    float* S = (float*)smraw;
    float* Gred = S + 32*400;
    {
        int nl = wn + (lane >> 2);
        #pragma unroll
        for (int jt = 0; jt < 13; jt++) {
            int j0 = wj + jt*8 + ((lane & 3) << 1);
            if (j0 < 392) {
                S[nl*400 + j0]       = acc[jt][0];
                S[nl*400 + j0 + 1]   = acc[jt][1];
                S[(nl+8)*400 + j0]   = acc[jt][2];
                S[(nl+8)*400 + j0+1] = acc[jt][3];
            }
        }
    }
    __syncthreads();
    {
        int n = t >> 3, h = t & 7;
        float* p = S + n*400 + h*49;
        const float* rb = rel_bias + (size_t)(nt0 + n)*49;
        float mx = -1e30f;
        for (int i = 0; i < 49; i++) {
            float lv = p[i] + __ldg(rb + i);
            p[i] = lv;
            mx = fmaxf(mx, lv);
        }
        float sum = 0.f;
        for (int i = 0; i < 49; i++) { float e = __expf(p[i] - mx); p[i] = e; sum += e; }
        float inv = 1.f / sum;
        for (int i = 0; i < 49; i++) p[i] *= inv;
    }
    __syncthreads();
    float g[36];
    #pragma unroll
    for (int k = 0; k < 36; k++) g[k] = 0.f;
    for (int pos = t; pos < 32*49; pos += 256) {
        int n = pos / 49, m = pos - n*49;
        float a[8];
        #pragma unroll
        for (int h = 0; h < 8; h++) a[h] = S[n*400 + h*49 + m];
        int k = 0;
        #pragma unroll
        for (int h = 0; h < 8; h++)
            #pragma unroll
            for (int h2 = h; h2 < 8; h2++) { g[k] += a[h]*a[h2]; k++; }
    }
    size_t ob = ((size_t)b*3136 + nt0)*392;
    for (int i = t; i < 32*392; i += 256) {
        int n = i / 392, c = i - n*392;
        g_attn[ob + i] = S[n*400 + c];
    }
    #pragma unroll
    for (int s = 16; s; s >>= 1)
        #pragma unroll
        for (int k = 0; k < 36; k++) g[k] += __shfl_xor_sync(0xffffffffu, g[k], s);
    if (lane == 0)
        #pragma unroll
        for (int k = 0; k < 36; k++) Gred[w*36 + k] = g[k];
    __syncthreads();
    if (t < 36) {
        float s = 0.f;
        #pragma unroll
        for (int ww = 0; ww < 8; ww++) s += Gred[ww*36 + t];
        g_part1[((size_t)b*98 + blockIdx.x)*36 + t] = s;
    }
}

// ---------------- 5. gn1 finalize from Gram ----------------
__global__ void k_gn1_final(const float* __restrict__ gs, const float* __restrict__ gb,
                            const float* __restrict__ ew) {
    int b = blockIdx.x, t = threadIdx.x;   // 64 threads
    __shared__ float M36[36];
    __shared__ float Mf[64];
    __shared__ float s1s[24], sqs[24];
    __shared__ float mg[3], rg[3];
    if (t < 36) {
        float s = 0.f;
        for (int nt = 0; nt < 98; nt++) s += g_part1[((size_t)b*98 + nt)*36 + t];
        M36[t] = s;
    }
    __syncthreads();
    if (t == 0) {
        int k = 0;
        for (int h = 0; h < 8; h++)
            for (int h2 = h; h2 < 8; h2++) { Mf[h*8+h2] = M36[k]; Mf[h2*8+h] = M36[k]; k++; }
    }
    __syncthreads();
    if (t < 24) {
        float wv[8], sw = 0.f;
        #pragma unroll
        for (int h = 0; h < 8; h++) { wv[h] = ew[t*8+h]; sw += wv[h]; }
        float sq = 0.f;
        #pragma unroll
        for (int h = 0; h < 8; h++)
            #pragma unroll
            for (int h2 = 0; h2 < 8; h2++) sq += wv[h]*wv[h2]*Mf[h*8+h2];
        s1s[t] = 3136.f * sw;
        sqs[t] = sq;
    }
    __syncthreads();
    if (t < 3) {
        float s1 = 0.f, sq = 0.f;
        for (int c = 0; c < 8; c++) { s1 += s1s[t*8+c]; sq += sqs[t*8+c]; }
        float cnt = 8.f*3136.f*49.f;
        float mean = s1/cnt;
        float var  = sq/cnt - mean*mean;
        mg[t] = mean;
        rg[t] = rsqrtf(var + 1e-5f);
    }
    __syncthreads();
    if (t < 24) {
        float A = rg[t>>3]*gs[t];
        g_ab1[(b*24 + t)*2]     = A;
        g_ab1[(b*24 + t)*2 + 1] = gb[t] - mg[t>>3]*A;
    }
}

// ---------------- stats finalize (gn2/gn3) ----------------
__global__ void k_stats_final(const float* __restrict__ gs, const float* __restrict__ gb,
                              float* __restrict__ ab, const float* __restrict__ part,
                              int G, int npart) {
    int b = blockIdx.x / G, g = blockIdx.x % G;
    const float* p = part + (size_t)(b*G + g)*npart*2;
    float sm = 0.f, sq = 0.f;
    for (int i = threadIdx.x; i < npart; i += 256) { sm += p[2*i]; sq += p[2*i+1]; }
    __shared__ float rs[256], rq[256];
    __shared__ float mean_s, rstd_s;
    int t = threadIdx.x;
    rs[t] = sm; rq[t] = sq;
    __syncthreads();
    for (int st = 128; st; st >>= 1) {
        if (t < st) { rs[t] += rs[t+st]; rq[t] += rq[t+st]; }
        __syncthreads();
    }
    if (!t) {
        float cnt  = 8.f * 3136.f * 49.f;
        float mean = rs[0] / cnt;
        float var  = rq[0] / cnt - mean*mean;
        mean_s = mean;
        rstd_s = rsqrtf(var + 1e-5f);
    }
    __syncthreads();
    if (t < 8) {
        int c = g*8 + t;
        float A = rstd_s * gs[c];
        int CH = G*8;
        ab[(b*CH + c)*2]     = A;
        ab[(b*CH + c)*2 + 1] = gb[c] - mean_s*A;
    }
}

// ---------------- 6. pass B v2: position-major expand + register-rolling dw -> gn2 partials ----------------
// smem: arow[2][392], hid[18][24][53], ew[192], ab[48], red[6*256]
#define B2_AROW 0
#define B2_HID  784
#define B2_EW   (784 + 22896)
#define B2_AB   (B2_EW + 192)
#define B2_RED  (B2_AB + 48)
#define B2_TOT  (B2_RED + 1536)
#define B2_SMEM (B2_TOT*4)
__global__ __launch_bounds__(256) void k_dw_gn2(const float* __restrict__ dw_w,
                                                const float* __restrict__ expand_w) {
    extern __shared__ float sm[];
    float* arow = sm + B2_AROW;
    float* hid  = sm + B2_HID;
    float* ew   = sm + B2_EW;
    float* ab   = sm + B2_AB;
    float* red  = sm + B2_RED;
    uint32_t sb = smem_u32(sm);
    int nt = blockIdx.x, b = blockIdx.y, t = threadIdx.x;
    int n0 = nt * 16;
    if (t < 192) ew[t] = expand_w[t];
    if (t >= 192 && t < 240) ab[t-192] = g_ab1[b*48 + (t-192)];
    // zero hid pad columns 0 and 50
    for (int i = t; i < 18*24; i += 256) {
        hid[i*53 + 0]  = 0.f;
        hid[i*53 + 50] = 0.f;
    }
    // prologue: load row 0 (n = n0-1)
    if (t < 98) {
        int n = n0 - 1;
        bool v = (n >= 0) && (n < 3136);
        const float* src = g_attn + ((size_t)b*3136 + (v ? n : 0))*392 + t*4;
        cpa16(sb + (B2_AROW + t*4)*4, src, v);
    }
    cp_commit();
    for (int r = 0; r < 18; r++) {
        if (r < 17) {
            if (t < 98) {
                int n = n0 + r;            // row r+1 => n0 - 1 + (r+1)
                bool v = (n >= 0) && (n < 3136);
                const float* src = g_attn + ((size_t)b*3136 + (v ? n : 0))*392 + t*4;
                cpa16(sb + (B2_AROW + ((r+1)&1)*392 + t*4)*4, src, v);
            }
            cp_commit();
            cp_wait1();
        } else cp_wait0();
        __syncthreads();
        // expand: 196 threads, m = t%49, cgroup = t/49 (4 groups of 6 channels)
        if (t < 196) {
            int m = t % 49, cg = t / 49;
            const float* ar = arow + (r & 1)*392;
            int n = n0 - 1 + r;
            bool rowvalid = (n >= 0) && (n < 3136);
            float a[8];
            #pragma unroll
            for (int h = 0; h < 8; h++) a[h] = ar[h*49 + m];
            #pragma unroll
            for (int j = 0; j < 6; j++) {
                int c = cg*6 + j;
                const float* wp = ew + c*8;
                float hs = 0.f;
                #pragma unroll
                for (int h = 0; h < 8; h++) hs += a[h]*wp[h];
                float v = rowvalid ? swishf(ab[c*2]*hs + ab[c*2+1]) : 0.f;
                hid[(r*24 + c)*53 + (m+1)] = v;
            }
        }
        __syncthreads();
    }
    // dw conv with register rolling: thread handles pairs (ny, c)
    float sk0 = 0.f, sk1 = 0.f, sk2 = 0.f, qk0 = 0.f, qk1 = 0.f, qk2 = 0.f;
    for (int pair = t; pair < 384; pair += 256) {
        int c = pair % 24, ny = pair / 24;
        float lw[9];
        #pragma unroll
        for (int i = 0; i < 9; i++) lw[i] = dw_w[c*9 + i];
        const float* h0 = hid + ((ny+0)*24 + c)*53;
        const float* h1 = hid + ((ny+1)*24 + c)*53;
        const float* h2 = hid + ((ny+2)*24 + c)*53;
        float a00 = h0[0], a01 = h0[1];
        float a10 = h1[0], a11 = h1[1];
        float a20 = h2[0], a21 = h2[1];
        float s = 0.f, q = 0.f;
        #pragma unroll 7
        for (int m = 0; m < 49; m++) {
            float a02 = h0[m+2], a12 = h1[m+2], a22 = h2[m+2];
            float acc = a00*lw[0] + a01*lw[1] + a02*lw[2]
                      + a10*lw[3] + a11*lw[4] + a12*lw[5]
                      + a20*lw[6] + a21*lw[7] + a22*lw[8];
            s += acc; q += acc*acc;
            a00 = a01; a01 = a02;
            a10 = a11; a11 = a12;
            a20 = a21; a21 = a22;
        }
        int g = c >> 3;
        if (g == 0)      { sk0 += s; qk0 += q; }
        else if (g == 1) { sk1 += s; qk1 += q; }
        else             { sk2 += s; qk2 += q; }
    }
    red[0*256 + t] = sk0; red[1*256 + t] = sk1; red[2*256 + t] = sk2;
    red[3*256 + t] = qk0; red[4*256 + t] = qk1; red[5*256 + t] = qk2;
    __syncthreads();
    for (int st = 128; st; st >>= 1) {
        if (t < st)
            #pragma unroll
            for (int g = 0; g < 6; g++) red[g*256 + t] += red[g*256 + t + st];
        __syncthreads();
    }
    if (t < 3) {
        g_part2[((b*3 + t)*196 + nt)*2]     = red[t*256];
        g_part2[((b*3 + t)*196 + nt)*2 + 1] = red[(t+3)*256];
    }
}

// ---------------- 7. pass C: expand+dw+norm2+swish, reduce -> attnF + gn3 ----------------
#define C_AT  0
#define C_HID 3920
#define C_DWS 8016
#define C_EW  17424
#define C_RW  17616
#define C_AB  17808
#define C_RED 17904
#define C_TOT (17904 + 512)
#define C_SMEM (C_TOT*4)
__global__ __launch_bounds__(256) void k_dla_out(const float* __restrict__ dw_w,
                                                 const float* __restrict__ expand_w,
                                                 const float* __restrict__ reduce_w) {
    extern __shared__ float sm[];
    float* at  = sm + C_AT;
    float* dws = sm + C_DWS;
    float* ew  = sm + C_EW;
    float* rw  = sm + C_RW;
    float* ab  = sm + C_AB;
    float* red = sm + C_RED;
    int nt = blockIdx.x, b = blockIdx.y, t = threadIdx.x;
    int w = t >> 5, lane = t & 31;
    float* hid = sm + C_HID + w*512;
    int n0 = nt * 8;
    if (t < 192) { ew[t] = expand_w[t]; rw[t] = reduce_w[t]; }
    if (t < 96) ab[t] = (t < 48) ? g_ab1[b*48 + t] : g_ab2[b*48 + (t-48)];
    for (int i = t; i < 10*392; i += 256) {
        int r = i / 392, m = i - r*392;
        int n = n0 - 1 + r;
        at[i] = (n >= 0 && n < 3136) ? g_attn[((size_t)b*3136 + n)*392 + m] : 0.f;
    }
    __syncthreads();
    #pragma unroll
    for (int k = 0; k < 3; k++) {
        int c = w + k*8;
        float A1 = ab[c*2], B1 = ab[c*2+1];
        float A2 = ab[48 + c*2], B2 = ab[49 + c*2];
        const float* wp = ew + c*8;
        for (int i = lane; i < 510; i += 32) {
            int r = i / 51, mm = i - r*51;
            int n = n0 - 1 + r;
            float v = 0.f;
            if (mm >= 1 && mm <= 49 && n >= 0 && n < 3136) {
                const float* sp = at + r*392 + (mm - 1);
                float hsum = 0.f;
                #pragma unroll
                for (int hh = 0; hh < 8; hh++) hsum += sp[hh*49] * wp[hh];
                v = swishf(A1*hsum + B1);
            }
            hid[i] = v;
        }
        __syncwarp();
        float lw[9];
        #pragma unroll
        for (int i = 0; i < 9; i++) lw[i] = dw_w[c*9 + i];
        for (int o = lane; o < 392; o += 32) {
            int ny = o / 49, m = o - ny*49;
            float a = 0.f;
            #pragma unroll
            for (int dy = 0; dy < 3; dy++)
                #pragma unroll
                for (int dx = 0; dx < 3; dx++)
                    a += hid[(ny+dy)*51 + m+dx] * lw[dy*3+dx];
            dws[(ny*24 + c)*49 + m] = swishf(A2*a + B2);
        }
        __syncwarp();
    }
    __syncthreads();
    float lsum = 0.f, lsq = 0.f;
    for (int o = t; o < 392; o += 256) {
        int ny = o / 49, m = o - ny*49;
        int n = n0 + ny;
        float in[24];
        #pragma unroll
        for (int c = 0; c < 24; c++) in[c] = dws[(ny*24 + c)*49 + m];
        size_t ob = ((size_t)b*3136 + n)*392 + m;
        #pragma unroll
        for (int h = 0; h < 8; h++) {
            float r = 0.f;
            #pragma unroll
            for (int c = 0; c < 24; c++) r += in[c] * rw[h*24 + c];
            __nv_bfloat16 hh, ll; bsplit(r, hh, ll);
            g_ath[ob + h*49] = hh;
            g_atl[ob + h*49] = ll;
            lsum += r; lsq += r*r;
        }
    }
    red[t] = lsum; red[256 + t] = lsq;
    __syncthreads();
    for (int st = 128; st; st >>= 1) {
        if (t < st) { red[t] += red[t+st]; red[256+t] += red[256+t+st]; }
        __syncthreads();
    }
    if (!t) {
        g_part3[(b*392 + nt)*2]     = red[0];
        g_part3[(b*392 + nt)*2 + 1] = red[256];
    }
}

// ---------------- 8. k_wvpfin: fused wvpsplit (blocks 0..3327) + wvpbias (3328..3343) ----------------
__global__ __launch_bounds__(256) void k_wvpfin(const float* __restrict__ proj_b) {
    __shared__ float tile[32][33];
    int blk = blockIdx.x;
    int t = threadIdx.x;
    if (blk < 3328) {
        int tj = blk % 13;
        int rest = blk / 13;
        int tc = rest & 15, b = rest >> 4;
        int a = t >> 5, q = t & 31;
        #pragma unroll
        for (int r = 0; r < 4; r++) {
            int jj = tj*32 + a + r*8, cc = tc*32 + q;
            float v = 0.f;
            if (jj < 392) v = g_Wvp[((size_t)b*392 + jj)*512 + cc] * g_ab3[(b*8 + jj/49)*2];
            tile[a + r*8][q] = v;
        }
        __syncthreads();
        #pragma unroll
        for (int r = 0; r < 4; r++) {
            int cc = tc*32 + a + r*8, jj = tj*32 + q;
            if (jj < 392) {
                float v = tile[q][a + r*8];
                __nv_bfloat16 h, l; bsplit(v, h, l);
                size_t o = ((size_t)b*512 + cc)*392 + jj;
                g_wvh[o] = h; g_wvl[o] = l;
            }
        }
    } else {
        int b = blk - 3328;
        #pragma unroll
        for (int cc = 0; cc < 2; cc++) {
            int c = t + cc*256;
            float acc = 0.f;
            for (int j = 0; j < 392; j++)
                acc += g_ab3[(b*8 + j/49)*2 + 1] * g_Wvp[((size_t)b*392 + j)*512 + c];
            g_bias2[b*512 + c] = acc + proj_b[c];
        }
    }
}

// ---------------- 9. GEMM2 (bf16x3 mma.sync) ----------------
#define G2_BUF 15360
#define G2_AH 0
#define G2_AL 5120
#define G2_BH 10240
#define G2_BL 12800
#define G2_SMEM (G2_BUF*2*2)
__device__ __forceinline__ void g2_load(uint32_t sb, int b, int nt0, int ct0,
                                        int kt, int p, int t) {
    int k0 = kt*32;
    uint32_t base = sb + (uint32_t)p*G2_BUF*2;
    #pragma unroll
    for (int rr = 0; rr < 2; rr++) {
        int idx = t + rr*256;
        int row = idx >> 2, q = idx & 3;
        int n = nt0 + row, j0 = k0 + q*8;
        bool v = (n < 3136) && (j0 < 392);
        size_t e = ((size_t)b*3136 + (n < 3136 ? n : 0))*392 + (j0 < 392 ? j0 : 0);
        uint32_t doff = (uint32_t)(row*40 + q*8)*2;
        cpa16(base + G2_AH*2 + doff, g_ath + e, v);
        cpa16(base + G2_AL*2 + doff, g_atl + e, v);
    }
    {
        int idx = t;
        int row = idx >> 2, q = idx & 3;
        int c = ct0 + row, j0 = k0 + q*8;
        bool v = j0 < 392;
        size_t e = ((size_t)b*512 + c)*392 + (v ? j0 : 0);
        uint32_t doff = (uint32_t)(row*40 + q*8)*2;
        cpa16(base + G2_BH*2 + doff, g_wvh + e, v);
        cpa16(base + G2_BL*2 + doff, g_wvl + e, v);
    }
}

__global__ __launch_bounds__(256) void k_gemm2_mma(float* __restrict__ out) {
    extern __shared__ __nv_bfloat16 dsm2[];
    uint32_t sb = smem_u32(dsm2);
    int b = blockIdx.z, nt0 = blockIdx.y*128, ct0 = blockIdx.x*64;
    int t = threadIdx.x, w = t >> 5, lane = t & 31;
    int wn = (w & 3)*32, wc = (w >> 2)*32;
    float acc[2][4][4];
    #pragma unroll
    for (int i = 0; i < 2; i++)
        #pragma unroll
        for (int j = 0; j < 4; j++)
            #pragma unroll
            for (int k = 0; k < 4; k++) acc[i][j][k] = 0.f;

    g2_load(sb, b, nt0, ct0, 0, 0, t);
    cp_commit();
    for (int kt = 0; kt < 13; kt++) {
        if (kt < 12) {
            g2_load(sb, b, nt0, ct0, kt+1, (kt+1) & 1, t);
            cp_commit();
            cp_wait1();
        } else cp_wait0();
        __syncthreads();
        uint32_t base = sb + (uint32_t)(kt & 1)*G2_BUF*2;
        #pragma unroll
        for (int kk = 0; kk < 2; kk++) {
            int kb = kk*16;
            uint32_t ah[2][4], al[2][4];
            #pragma unroll
            for (int mt = 0; mt < 2; mt++) {
                int row = wn + mt*16 + (lane & 15);
                int col = kb + ((lane & 16) ? 8 : 0);
                uint32_t off = (uint32_t)(row*40 + col)*2;
                ldm_x4(ah[mt], base + G2_AH*2 + off);
                ldm_x4(al[mt], base + G2_AL*2 + off);
            }
            uint32_t bh[4][2], bl[4][2];
            #pragma unroll
            for (int p = 0; p < 2; p++) {
                int crow = wc + p*16 + (lane & 7) + ((lane & 16) ? 8 : 0);
                int col = kb + ((lane & 8) ? 8 : 0);
                uint32_t off = (uint32_t)(crow*40 + col)*2;
                uint32_t r4[4];
                ldm_x4(r4, base + G2_BH*2 + off);
                bh[2*p][0]=r4[0]; bh[2*p][1]=r4[1]; bh[2*p+1][0]=r4[2]; bh[2*p+1][1]=r4[3];
                ldm_x4(r4, base + G2_BL*2 + off);
                bl[2*p][0]=r4[0]; bl[2*p][1]=r4[1]; bl[2*p+1][0]=r4[2]; bl[2*p+1][1]=r4[3];
            }
            #pragma unroll
            for (int mt = 0; mt < 2; mt++)
                #pragma unroll
                for (int ct = 0; ct < 4; ct++) {
                    mma_bf16(acc[mt][ct], ah[mt], bh[ct]);
                    mma_bf16(acc[mt][ct], al[mt], bh[ct]);
                    mma_bf16(acc[mt][ct], ah[mt], bl[ct]);
                }
        }
        __syncthreads();
    }
    int nrow = nt0 + wn + (lane >> 2);
    #pragma unroll
    for (int mt = 0; mt < 2; mt++) {
        #pragma unroll
        for (int ct = 0; ct < 4; ct++) {
            int c0 = ct0 + wc + ct*8 + ((lane & 3) << 1);
            float b0 = g_bias2[b*512 + c0];
            float b1 = g_bias2[b*512 + c0 + 1];
            #pragma unroll
            for (int half = 0; half < 2; half++) {
                int n = nrow + mt*16 + half*8;
                if (n < 3136) {
                    size_t o = ((size_t)b*3136 + n)*512 + c0;
                    *(float2*)&out[o] = make_float2(acc[mt][ct][half*2] + b0,
                                                    acc[mt][ct][half*2+1] + b1);
                }
            }
        }
    }
}

// ---------------- launcher ----------------
extern "C" void kernel_launch(void* const* d_in, const int* in_sizes, int n_in,
                              void* d_out, int out_size) {
    const float* x        = (const float*)d_in[0];
    const float* q_w      = (const float*)d_in[1];
    const float* down_w   = (const float*)d_in[2];
    const float* kv_w     = (const float*)d_in[3];
    const float* proj_w   = (const float*)d_in[4];
    const float* proj_b   = (const float*)d_in[5];
    const float* rel_bias = (const float*)d_in[6];
    const float* expand_w = (const float*)d_in[7];
    const float* gn1_s    = (const float*)d_in[8];
    const float* gn1_b    = (const float*)d_in[9];
    const float* dw_w     = (const float*)d_in[10];
    const float* gn2_s    = (const float*)d_in[11];
    const float* gn2_b    = (const float*)d_in[12];
    const float* reduce_w = (const float*)d_in[13];
    const float* gn3_s    = (const float*)d_in[14];
    const float* gn3_b    = (const float*)d_in[15];
    float* out = (float*)d_out;

    float *ab2, *ab3, *p2, *p3;
    cudaGetSymbolAddress((void**)&ab2, g_ab2);
    cudaGetSymbolAddress((void**)&ab3, g_ab3);
    cudaGetSymbolAddress((void**)&p2, g_part2);
    cudaGetSymbolAddress((void**)&p3, g_part3);

    cudaFuncSetAttribute(k_gemm1_fused, cudaFuncAttributeMaxDynamicSharedMemorySize, G1_SMEM);
    cudaFuncSetAttribute(k_gemm2_mma, cudaFuncAttributeMaxDynamicSharedMemorySize, G2_SMEM);
    cudaFuncSetAttribute(k_dw_gn2,    cudaFuncAttributeMaxDynamicSharedMemorySize, B2_SMEM);
    cudaFuncSetAttribute(k_dla_out,   cudaFuncAttributeMaxDynamicSharedMemorySize, C_SMEM);

    k_prep<<<33280, 256>>>(x, down_w);
    k_kv  <<<dim3(4, 7, BB), 256>>>(kv_w);
    k_qkvw<<<1152, 256>>>(q_w, proj_w);
    k_gemm1_fused<<<dim3(98, BB), 256, G1_SMEM>>>(rel_bias);
    k_gn1_final<<<BB, 64>>>(gn1_s, gn1_b, expand_w);
    k_dw_gn2<<<dim3(196, BB), 256, B2_SMEM>>>(dw_w, expand_w);
    k_stats_final<<<BB*3, 256>>>(gn2_s, gn2_b, ab2, p2, 3, 196);
    k_dla_out<<<dim3(392, BB), 256, C_SMEM>>>(dw_w, expand_w, reduce_w);
    k_stats_final<<<BB, 256>>>(gn3_s, gn3_b, ab3, p3, 1, 392);
    k_wvpfin<<<3344, 256>>>(proj_b);
    k_gemm2_mma<<<dim3(8, 25, BB), 256, G2_SMEM>>>(out);
}

// round 17
// speedup vs baseline: 1.2202x; 1.1492x over previous
#include <cuda_runtime.h>
#include <cuda_bf16.h>
#include <math.h>
#include <stdint.h>

#define BB    16
#define CCH   512
#define NN    3136
#define NKK   49
#define HEADS 8
#define JJ    392
#define HIDC  24
#define SCALE 0.125f

// ---------------- device scratch ----------------
__device__ float g_kvx[BB*NKK*CCH];
__device__ float g_kv [BB*NKK*1024];
__device__ float g_Wvp[BB*JJ*CCH];
__device__ __nv_bfloat16 g_xTh[(size_t)BB*NN*CCH];
__device__ __nv_bfloat16 g_xTl[(size_t)BB*NN*CCH];
__device__ __nv_bfloat16 g_wqh[BB*JJ*CCH];
__device__ __nv_bfloat16 g_wvh[BB*CCH*JJ];
__device__ __nv_bfloat16 g_wvl[BB*CCH*JJ];
__device__ float g_attn[(size_t)BB*NN*JJ];
__device__ __nv_bfloat16 g_ath[(size_t)BB*NN*JJ];
__device__ __nv_bfloat16 g_atl[(size_t)BB*NN*JJ];
__device__ float g_part1[BB*98*36];
__device__ float g_part2[BB*3*196*2];
__device__ float g_part3[BB*392*2];
__device__ float g_ab1[BB*HIDC*2];
__device__ float g_ab2[BB*HIDC*2];
__device__ float g_ab3[BB*HEADS*2];
__device__ float g_bias2[BB*CCH];

__device__ __forceinline__ float swishf(float x) { return x / (1.f + __expf(-x)); }

__device__ __forceinline__ void bsplit(float v, __nv_bfloat16& h, __nv_bfloat16& l) {
    h = __float2bfloat16(v);
    l = __float2bfloat16(v - __bfloat162float(h));
}

__device__ __forceinline__ uint32_t smem_u32(const void* p) {
    uint32_t a;
    asm("{ .reg .u64 t; cvta.to.shared.u64 t, %1; cvt.u32.u64 %0, t; }" : "=r"(a) : "l"(p));
    return a;
}
__device__ __forceinline__ void ldm_x4(uint32_t* r, uint32_t addr) {
    asm volatile("ldmatrix.sync.aligned.m8n8.x4.shared.b16 {%0,%1,%2,%3}, [%4];"
        : "=r"(r[0]), "=r"(r[1]), "=r"(r[2]), "=r"(r[3]) : "r"(addr));
}
__device__ __forceinline__ void ldm_x2(uint32_t* r, uint32_t addr) {
    asm volatile("ldmatrix.sync.aligned.m8n8.x2.shared.b16 {%0,%1}, [%2];"
        : "=r"(r[0]), "=r"(r[1]) : "r"(addr));
}
__device__ __forceinline__ void mma_bf16(float* c, const uint32_t* a, const uint32_t* b) {
    asm volatile(
        "mma.sync.aligned.m16n8k16.row.col.f32.bf16.bf16.f32 "
        "{%0,%1,%2,%3}, {%4,%5,%6,%7}, {%8,%9}, {%0,%1,%2,%3};"
        : "+f"(c[0]), "+f"(c[1]), "+f"(c[2]), "+f"(c[3])
        : "r"(a[0]), "r"(a[1]), "r"(a[2]), "r"(a[3]), "r"(b[0]), "r"(b[1]));
}
__device__ __forceinline__ void cpa16(uint32_t dst, const void* src, bool v) {
    int sz = v ? 16 : 0;
    asm volatile("cp.async.cg.shared.global [%0], [%1], 16, %2;"
        :: "r"(dst), "l"(src), "r"(sz) : "memory");
}
__device__ __forceinline__ void cp_commit() {
    asm volatile("cp.async.commit_group;" ::: "memory");
}
__device__ __forceinline__ void cp_wait1() {
    asm volatile("cp.async.wait_group 1;" ::: "memory");
}
__device__ __forceinline__ void cp_wait0() {
    asm volatile("cp.async.wait_group 0;" ::: "memory");
}

// ---------------- 1. k_prep: fused xsplit + down ----------------
__global__ __launch_bounds__(256) void k_prep(const float* __restrict__ x,
                                              const float* __restrict__ down_w) {
    __shared__ float sh[3200];
    int blk = blockIdx.x;
    int t = threadIdx.x;
    if (blk < 25088) {
        int tn = blk % 98;
        int rest = blk / 98;
        int tc = rest & 15, b = rest >> 4;
        float (*tile)[33] = (float(*)[33])sh;
        int a = t >> 5, q = t & 31;
        #pragma unroll
        for (int r = 0; r < 4; r++) {
            int cc = tc*32 + a + r*8, nn = tn*32 + q;
            tile[a + r*8][q] = x[((size_t)b*512 + cc)*3136 + nn];
        }
        __syncthreads();
        #pragma unroll
        for (int r = 0; r < 4; r++) {
            int nn = tn*32 + a + r*8, cc = tc*32 + q;
            float v = tile[q][a + r*8];
            __nv_bfloat16 h, l; bsplit(v, h, l);
            size_t o = ((size_t)b*3136 + nn)*512 + cc;
            g_xTh[o] = h; g_xTl[o] = l;
        }
    } else {
        int bc = blk - 25088, c = bc & 511, b = bc >> 9;
        float* plane = sh;
        float* w = sh + 3136;
        const float* xp = x + (size_t)bc * 3136;
        for (int i = t; i < 3136; i += 256) plane[i] = xp[i];
        if (t < 64) w[t] = down_w[c*64 + t];
        __syncthreads();
        if (t < 49) {
            int my = t / 7, mx = t % 7;
            float s = 0.f;
            #pragma unroll
            for (int i = 0; i < 8; i++)
                #pragma unroll
                for (int j = 0; j < 8; j++)
                    s += plane[(my*8+i)*56 + mx*8 + j] * w[i*8+j];
            g_kvx[(b*49 + t)*512 + c] = s;
        }
    }
}

// ---------------- 2. kv = kvx @ kv_w ----------------
__global__ void k_kv(const float* __restrict__ kv_w) {
    int b = blockIdx.z, m0 = blockIdx.y * 7, oc = blockIdx.x;
    __shared__ float a[7][512];
    for (int i = threadIdx.x; i < 7*512; i += 256)
        a[i >> 9][i & 511] = g_kvx[(b*49 + m0 + (i >> 9))*512 + (i & 511)];
    __syncthreads();
    int o = oc*256 + threadIdx.x;
    float acc[7] = {0,0,0,0,0,0,0};
    for (int c = 0; c < 512; c++) {
        float w = kv_w[c*1024 + o];
        #pragma unroll
        for (int mm = 0; mm < 7; mm++) acc[mm] += a[mm][c] * w;
    }
    #pragma unroll
    for (int mm = 0; mm < 7; mm++)
        g_kv[(b*49 + m0 + mm)*1024 + o] = acc[mm];
}

// ---------------- 3. k_qkvw: fused wqk_split + wvp ----------------
__global__ __launch_bounds__(256) void k_qkvw(const float* __restrict__ q_w,
                                              const float* __restrict__ proj_w) {
    __shared__ float sh[3136];
    int blk = blockIdx.x;
    int t = threadIdx.x;
    if (blk < 256) {
        int half = blk & 1, h = (blk >> 1) & 7, b = blk >> 4;
        float (*ks)[64] = (float(*)[64])sh;
        for (int i = t; i < 49*64; i += 256)
            ks[i >> 6][i & 63] = g_kv[(b*49 + (i >> 6))*1024 + h*64 + (i & 63)];
        __syncthreads();
        int cin = half*256 + t;
        float acc[49];
        #pragma unroll
        for (int m = 0; m < 49; m++) acc[m] = 0.f;
        const float4* q4 = (const float4*)(q_w + (size_t)cin*512 + h*64);
        const float4* ks4 = (const float4*)&ks[0][0];
        for (int d4 = 0; d4 < 16; d4++) {
            float4 q = __ldg(q4 + d4);
            #pragma unroll
            for (int m = 0; m < 49; m++) {
                float4 k = ks4[m*16 + d4];
                acc[m] += q.x*k.x + q.y*k.y + q.z*k.z + q.w*k.w;
            }
        }
        size_t obase = ((size_t)b*392 + h*49)*512 + cin;
        #pragma unroll
        for (int m = 0; m < 49; m++)
            g_wqh[obase + (size_t)m*512] = __float2bfloat16(acc[m] * SCALE);
    } else {
        int q = blk - 256;
        int mc = (q % 7) * 7, h = (q / 7) & 7, b = q / 56;
        float (*vs)[64] = (float(*)[64])sh;
        for (int i = t; i < 7*64; i += 256)
            vs[i >> 6][i & 63] = g_kv[(b*49 + mc + (i >> 6))*1024 + 512 + h*64 + (i & 63)];
        __syncthreads();
        float acc[7][2] = {{0}};
        for (int d = 0; d < 64; d++) {
            float w0 = proj_w[(h*64+d)*512 + t];
            float w1 = proj_w[(h*64+d)*512 + 256 + t];
            #pragma unroll
            for (int mm = 0; mm < 7; mm++) {
                float vv = vs[mm][d];
                acc[mm][0] += vv * w0;
                acc[mm][1] += vv * w1;
            }
        }
        #pragma unroll
        for (int mm = 0; mm < 7; mm++) {
            int j = h*49 + mc + mm;
            g_Wvp[(b*392 + j)*512 + t]       = acc[mm][0];
            g_Wvp[(b*392 + j)*512 + 256 + t] = acc[mm][1];
        }
    }
}

// ---------------- 4. GEMM1 fused (bf16x2; 32n x 416j tiles, k-tile 32, 2 CTAs/SM) ----------------
#define G1_BUFSZ 38400u
#define G1_AHOFF 0u
#define G1_ALOFF 2560u
#define G1_BHOFF 5120u
#define G1_SMEM  76800
__device__ __forceinline__ void g1f_load(uint32_t sb, int b, int nt0, int kt, int p, int t) {
    int k0 = kt*32;
    uint32_t base = sb + (uint32_t)p*G1_BUFSZ;
    {
        int hl = t >= 128;
        int ii = t & 127;
        int row = ii >> 2, q = ii & 3;
        size_t e = ((size_t)b*3136 + nt0 + row)*512 + k0 + q*8;
        uint32_t doff = (uint32_t)(row*40 + q*8)*2;
        cpa16(base + (hl ? G1_ALOFF : G1_AHOFF) + doff, (hl ? g_xTl : g_xTh) + e, true);
    }
    #pragma unroll
    for (int rr = 0; rr < 7; rr++) {
        int idx = rr*256 + t;
        if (idx < 1664) {
            int row = idx >> 2, q = idx & 3;
            bool v = row < 392;
            size_t e = ((size_t)b*392 + (v ? row : 0))*512 + k0 + q*8;
            uint32_t doff = (uint32_t)(row*40 + q*8)*2;
            cpa16(base + G1_BHOFF + doff, g_wqh + e, v);
        }
    }
}

__global__ __launch_bounds__(256, 2) void k_gemm1_fused(const float* __restrict__ rel_bias) {
    extern __shared__ char smraw[];
    uint32_t sb = smem_u32(smraw);
    int b = blockIdx.y, nt0 = blockIdx.x * 32;
    int t = threadIdx.x, w = t >> 5, lane = t & 31;
    int wn = (w & 1)*16, wj = (w >> 1)*104;
    float acc[13][4];
    #pragma unroll
    for (int j = 0; j < 13; j++)
        #pragma unroll
        for (int k = 0; k < 4; k++) acc[j][k] = 0.f;

    g1f_load(sb, b, nt0, 0, 0, t);
    cp_commit();
    for (int kt = 0; kt < 16; kt++) {
        if (kt < 15) {
            g1f_load(sb, b, nt0, kt+1, (kt+1) & 1, t);
            cp_commit();
            cp_wait1();
        } else cp_wait0();
        __syncthreads();
        uint32_t base = sb + (uint32_t)(kt & 1)*G1_BUFSZ;
        #pragma unroll
        for (int kk = 0; kk < 2; kk++) {
            int kb = kk*16;
            uint32_t ah[4], al[4];
            int arow = wn + (lane & 15);
            int acol = kb + ((lane & 16) ? 8 : 0);
            ldm_x4(ah, base + G1_AHOFF + (uint32_t)(arow*40 + acol)*2);
            ldm_x4(al, base + G1_ALOFF + (uint32_t)(arow*40 + acol)*2);
            #pragma unroll
            for (int p2 = 0; p2 < 6; p2++) {
                int jrow = wj + p2*16 + (lane & 7) + ((lane & 16) ? 8 : 0);
                int col = kb + ((lane & 8) ? 8 : 0);
                uint32_t off = (uint32_t)(jrow*40 + col)*2;
                uint32_t rh[4];
                ldm_x4(rh, base + G1_BHOFF + off);
                #pragma unroll
                for (int e = 0; e < 2; e++) {
                    mma_bf16(acc[2*p2+e], ah, &rh[2*e]);
                    mma_bf16(acc[2*p2+e], al, &rh[2*e]);
                }
            }
            {
                int jrow = wj + 96 + (lane & 7);
                int col = kb + ((lane & 8) ? 8 : 0);
                uint32_t off = (uint32_t)(jrow*40 + col)*2;
                uint32_t bh2[2];
                ldm_x2(bh2, base + G1_BHOFF + off);
                mma_bf16(acc[12], ah, bh2);
                mma_bf16(acc[12], al, bh2);
            }
        }
        __syncthreads();
    }
    float* S = (float*)smraw;
    float* Gred = S + 32*400;
    {
        int nl = wn + (lane >> 2);
        #pragma unroll
        for (int jt = 0; jt < 13; jt++) {
            int j0 = wj + jt*8 + ((lane & 3) << 1);
            if (j0 < 392) {
                S[nl*400 + j0]       = acc[jt][0];
                S[nl*400 + j0 + 1]   = acc[jt][1];
                S[(nl+8)*400 + j0]   = acc[jt][2];
                S[(nl+8)*400 + j0+1] = acc[jt][3];
            }
        }
    }
    __syncthreads();
    {
        int n = t >> 3, h = t & 7;
        float* p = S + n*400 + h*49;
        const float* rb = rel_bias + (size_t)(nt0 + n)*49;
        float mx = -1e30f;
        for (int i = 0; i < 49; i++) {
            float lv = p[i] + __ldg(rb + i);
            p[i] = lv;
            mx = fmaxf(mx, lv);
        }
        float sum = 0.f;
        for (int i = 0; i < 49; i++) { float e = __expf(p[i] - mx); p[i] = e; sum += e; }
        float inv = 1.f / sum;
        for (int i = 0; i < 49; i++) p[i] *= inv;
    }
    __syncthreads();
    float g[36];
    #pragma unroll
    for (int k = 0; k < 36; k++) g[k] = 0.f;
    for (int pos = t; pos < 32*49; pos += 256) {
        int n = pos / 49, m = pos - n*49;
        float a[8];
        #pragma unroll
        for (int h = 0; h < 8; h++) a[h] = S[n*400 + h*49 + m];
        int k = 0;
        #pragma unroll
        for (int h = 0; h < 8; h++)
            #pragma unroll
            for (int h2 = h; h2 < 8; h2++) { g[k] += a[h]*a[h2]; k++; }
    }
    size_t ob = ((size_t)b*3136 + nt0)*392;
    for (int i = t; i < 32*392; i += 256) {
        int n = i / 392, c = i - n*392;
        g_attn[ob + i] = S[n*400 + c];
    }
    #pragma unroll
    for (int s = 16; s; s >>= 1)
        #pragma unroll
        for (int k = 0; k < 36; k++) g[k] += __shfl_xor_sync(0xffffffffu, g[k], s);
    if (lane == 0)
        #pragma unroll
        for (int k = 0; k < 36; k++) Gred[w*36 + k] = g[k];
    __syncthreads();
    if (t < 36) {
        float s = 0.f;
        #pragma unroll
        for (int ww = 0; ww < 8; ww++) s += Gred[ww*36 + t];
        g_part1[((size_t)b*98 + blockIdx.x)*36 + t] = s;
    }
}

// ---------------- 5. gn1 finalize from Gram ----------------
__global__ void k_gn1_final(const float* __restrict__ gs, const float* __restrict__ gb,
                            const float* __restrict__ ew) {
    int b = blockIdx.x, t = threadIdx.x;   // 64 threads
    __shared__ float M36[36];
    __shared__ float Mf[64];
    __shared__ float s1s[24], sqs[24];
    __shared__ float mg[3], rg[3];
    if (t < 36) {
        float s = 0.f;
        for (int nt = 0; nt < 98; nt++) s += g_part1[((size_t)b*98 + nt)*36 + t];
        M36[t] = s;
    }
    __syncthreads();
    if (t == 0) {
        int k = 0;
        for (int h = 0; h < 8; h++)
            for (int h2 = h; h2 < 8; h2++) { Mf[h*8+h2] = M36[k]; Mf[h2*8+h] = M36[k]; k++; }
    }
    __syncthreads();
    if (t < 24) {
        float wv[8], sw = 0.f;
        #pragma unroll
        for (int h = 0; h < 8; h++) { wv[h] = ew[t*8+h]; sw += wv[h]; }
        float sq = 0.f;
        #pragma unroll
        for (int h = 0; h < 8; h++)
            #pragma unroll
            for (int h2 = 0; h2 < 8; h2++) sq += wv[h]*wv[h2]*Mf[h*8+h2];
        s1s[t] = 3136.f * sw;
        sqs[t] = sq;
    }
    __syncthreads();
    if (t < 3) {
        float s1 = 0.f, sq = 0.f;
        for (int c = 0; c < 8; c++) { s1 += s1s[t*8+c]; sq += sqs[t*8+c]; }
        float cnt = 8.f*3136.f*49.f;
        float mean = s1/cnt;
        float var  = sq/cnt - mean*mean;
        mg[t] = mean;
        rg[t] = rsqrtf(var + 1e-5f);
    }
    __syncthreads();
    if (t < 24) {
        float A = rg[t>>3]*gs[t];
        g_ab1[(b*24 + t)*2]     = A;
        g_ab1[(b*24 + t)*2 + 1] = gb[t] - mg[t>>3]*A;
    }
}

// ---------------- stats finalize (gn2/gn3) ----------------
__global__ void k_stats_final(const float* __restrict__ gs, const float* __restrict__ gb,
                              float* __restrict__ ab, const float* __restrict__ part,
                              int G, int npart) {
    int b = blockIdx.x / G, g = blockIdx.x % G;
    const float* p = part + (size_t)(b*G + g)*npart*2;
    float sm = 0.f, sq = 0.f;
    for (int i = threadIdx.x; i < npart; i += 256) { sm += p[2*i]; sq += p[2*i+1]; }
    __shared__ float rs[256], rq[256];
    __shared__ float mean_s, rstd_s;
    int t = threadIdx.x;
    rs[t] = sm; rq[t] = sq;
    __syncthreads();
    for (int st = 128; st; st >>= 1) {
        if (t < st) { rs[t] += rs[t+st]; rq[t] += rq[t+st]; }
        __syncthreads();
    }
    if (!t) {
        float cnt  = 8.f * 3136.f * 49.f;
        float mean = rs[0] / cnt;
        float var  = rq[0] / cnt - mean*mean;
        mean_s = mean;
        rstd_s = rsqrtf(var + 1e-5f);
    }
    __syncthreads();
    if (t < 8) {
        int c = g*8 + t;
        float A = rstd_s * gs[c];
        int CH = G*8;
        ab[(b*CH + c)*2]     = A;
        ab[(b*CH + c)*2 + 1] = gb[c] - mean_s*A;
    }
}

// ---------------- 6. pass B v2: position-major expand + register-rolling dw -> gn2 partials ----------------
#define B2_AROW 0
#define B2_HID  784
#define B2_EW   (784 + 22896)
#define B2_AB   (B2_EW + 192)
#define B2_RED  (B2_AB + 48)
#define B2_TOT  (B2_RED + 1536)
#define B2_SMEM (B2_TOT*4)
__global__ __launch_bounds__(256) void k_dw_gn2(const float* __restrict__ dw_w,
                                                const float* __restrict__ expand_w) {
    extern __shared__ float sm[];
    float* arow = sm + B2_AROW;
    float* hid  = sm + B2_HID;
    float* ew   = sm + B2_EW;
    float* ab   = sm + B2_AB;
    float* red  = sm + B2_RED;
    uint32_t sb = smem_u32(sm);
    int nt = blockIdx.x, b = blockIdx.y, t = threadIdx.x;
    int n0 = nt * 16;
    if (t < 192) ew[t] = expand_w[t];
    if (t >= 192 && t < 240) ab[t-192] = g_ab1[b*48 + (t-192)];
    for (int i = t; i < 18*24; i += 256) {
        hid[i*53 + 0]  = 0.f;
        hid[i*53 + 50] = 0.f;
    }
    if (t < 98) {
        int n = n0 - 1;
        bool v = (n >= 0) && (n < 3136);
        const float* src = g_attn + ((size_t)b*3136 + (v ? n : 0))*392 + t*4;
        cpa16(sb + (B2_AROW + t*4)*4, src, v);
    }
    cp_commit();
    for (int r = 0; r < 18; r++) {
        if (r < 17) {
            if (t < 98) {
                int n = n0 + r;
                bool v = (n >= 0) && (n < 3136);
                const float* src = g_attn + ((size_t)b*3136 + (v ? n : 0))*392 + t*4;
                cpa16(sb + (B2_AROW + ((r+1)&1)*392 + t*4)*4, src, v);
            }
            cp_commit();
            cp_wait1();
        } else cp_wait0();
        __syncthreads();
        if (t < 196) {
            int m = t % 49, cg = t / 49;
            const float* ar = arow + (r & 1)*392;
            int n = n0 - 1 + r;
            bool rowvalid = (n >= 0) && (n < 3136);
            float a[8];
            #pragma unroll
            for (int h = 0; h < 8; h++) a[h] = ar[h*49 + m];
            #pragma unroll
            for (int j = 0; j < 6; j++) {
                int c = cg*6 + j;
                const float* wp = ew + c*8;
                float hs = 0.f;
                #pragma unroll
                for (int h = 0; h < 8; h++) hs += a[h]*wp[h];
                float v = rowvalid ? swishf(ab[c*2]*hs + ab[c*2+1]) : 0.f;
                hid[(r*24 + c)*53 + (m+1)] = v;
            }
        }
        __syncthreads();
    }
    float sk0 = 0.f, sk1 = 0.f, sk2 = 0.f, qk0 = 0.f, qk1 = 0.f, qk2 = 0.f;
    for (int pair = t; pair < 384; pair += 256) {
        int c = pair % 24, ny = pair / 24;
        float lw[9];
        #pragma unroll
        for (int i = 0; i < 9; i++) lw[i] = dw_w[c*9 + i];
        const float* h0 = hid + ((ny+0)*24 + c)*53;
        const float* h1 = hid + ((ny+1)*24 + c)*53;
        const float* h2 = hid + ((ny+2)*24 + c)*53;
        float a00 = h0[0], a01 = h0[1];
        float a10 = h1[0], a11 = h1[1];
        float a20 = h2[0], a21 = h2[1];
        float s = 0.f, q = 0.f;
        #pragma unroll 7
        for (int m = 0; m < 49; m++) {
            float a02 = h0[m+2], a12 = h1[m+2], a22 = h2[m+2];
            float acc = a00*lw[0] + a01*lw[1] + a02*lw[2]
                      + a10*lw[3] + a11*lw[4] + a12*lw[5]
                      + a20*lw[6] + a21*lw[7] + a22*lw[8];
            s += acc; q += acc*acc;
            a00 = a01; a01 = a02;
            a10 = a11; a11 = a12;
            a20 = a21; a21 = a22;
        }
        int g = c >> 3;
        if (g == 0)      { sk0 += s; qk0 += q; }
        else if (g == 1) { sk1 += s; qk1 += q; }
        else             { sk2 += s; qk2 += q; }
    }
    red[0*256 + t] = sk0; red[1*256 + t] = sk1; red[2*256 + t] = sk2;
    red[3*256 + t] = qk0; red[4*256 + t] = qk1; red[5*256 + t] = qk2;
    __syncthreads();
    for (int st = 128; st; st >>= 1) {
        if (t < st)
            #pragma unroll
            for (int g = 0; g < 6; g++) red[g*256 + t] += red[g*256 + t + st];
        __syncthreads();
    }
    if (t < 3) {
        g_part2[((b*3 + t)*196 + nt)*2]     = red[t*256];
        g_part2[((b*3 + t)*196 + nt)*2 + 1] = red[(t+3)*256];
    }
}

// ---------------- 7. pass C v2: position-major expand + register-rolling dw+norm2, reduce -> attnF + gn3 ----------------
// smem (floats): arow[2][392], hid[10][24][53]=12720, dws[8][24][49]=9408, ew 192, rw 192, ab 96, red 512
#define C2_AROW 0
#define C2_HID  784
#define C2_DWS  (784 + 12720)
#define C2_EW   (C2_DWS + 9408)
#define C2_RW   (C2_EW + 192)
#define C2_AB   (C2_RW + 192)
#define C2_RED  (C2_AB + 96)
#define C2_TOT  (C2_RED + 512)
#define C2_SMEM (C2_TOT*4)
__global__ __launch_bounds__(256) void k_dla_out(const float* __restrict__ dw_w,
                                                 const float* __restrict__ expand_w,
                                                 const float* __restrict__ reduce_w) {
    extern __shared__ float sm[];
    float* arow = sm + C2_AROW;
    float* hid  = sm + C2_HID;
    float* dws  = sm + C2_DWS;
    float* ew   = sm + C2_EW;
    float* rw   = sm + C2_RW;
    float* ab   = sm + C2_AB;
    float* red  = sm + C2_RED;
    uint32_t sb = smem_u32(sm);
    int nt = blockIdx.x, b = blockIdx.y, t = threadIdx.x;
    int n0 = nt * 8;
    if (t < 192) { ew[t] = expand_w[t]; rw[t] = reduce_w[t]; }
    if (t >= 192 && t < 240) {
        int i = t - 192;
        ab[i] = g_ab1[b*48 + i];
        ab[48 + i] = g_ab2[b*48 + i];
    }
    for (int i = t; i < 10*24; i += 256) {
        hid[i*53 + 0]  = 0.f;
        hid[i*53 + 50] = 0.f;
    }
    if (t < 98) {
        int n = n0 - 1;
        bool v = (n >= 0) && (n < 3136);
        const float* src = g_attn + ((size_t)b*3136 + (v ? n : 0))*392 + t*4;
        cpa16(sb + (C2_AROW + t*4)*4, src, v);
    }
    cp_commit();
    for (int r = 0; r < 10; r++) {
        if (r < 9) {
            if (t < 98) {
                int n = n0 + r;
                bool v = (n >= 0) && (n < 3136);
                const float* src = g_attn + ((size_t)b*3136 + (v ? n : 0))*392 + t*4;
                cpa16(sb + (C2_AROW + ((r+1)&1)*392 + t*4)*4, src, v);
            }
            cp_commit();
            cp_wait1();
        } else cp_wait0();
        __syncthreads();
        if (t < 196) {
            int m = t % 49, cg = t / 49;
            const float* ar = arow + (r & 1)*392;
            int n = n0 - 1 + r;
            bool rowvalid = (n >= 0) && (n < 3136);
            float a[8];
            #pragma unroll
            for (int h = 0; h < 8; h++) a[h] = ar[h*49 + m];
            #pragma unroll
            for (int j = 0; j < 6; j++) {
                int c = cg*6 + j;
                const float* wp = ew + c*8;
                float hs = 0.f;
                #pragma unroll
                for (int h = 0; h < 8; h++) hs += a[h]*wp[h];
                float v = rowvalid ? swishf(ab[c*2]*hs + ab[c*2+1]) : 0.f;
                hid[(r*24 + c)*53 + (m+1)] = v;
            }
        }
        __syncthreads();
    }
    // dw + norm2 + swish: 192 pairs (ny 0..7, c 0..23)
    if (t < 192) {
        int c = t % 24, ny = t / 24;
        float lw[9];
        #pragma unroll
        for (int i = 0; i < 9; i++) lw[i] = dw_w[c*9 + i];
        float A2 = ab[48 + c*2], B2 = ab[49 + c*2];
        const float* h0 = hid + ((ny+0)*24 + c)*53;
        const float* h1 = hid + ((ny+1)*24 + c)*53;
        const float* h2 = hid + ((ny+2)*24 + c)*53;
        float* dp = dws + (ny*24 + c)*49;
        float a00 = h0[0], a01 = h0[1];
        float a10 = h1[0], a11 = h1[1];
        float a20 = h2[0], a21 = h2[1];
        #pragma unroll 7
        for (int m = 0; m < 49; m++) {
            float a02 = h0[m+2], a12 = h1[m+2], a22 = h2[m+2];
            float acc = a00*lw[0] + a01*lw[1] + a02*lw[2]
                      + a10*lw[3] + a11*lw[4] + a12*lw[5]
                      + a20*lw[6] + a21*lw[7] + a22*lw[8];
            dp[m] = swishf(A2*acc + B2);
            a00 = a01; a01 = a02;
            a10 = a11; a11 = a12;
            a20 = a21; a21 = a22;
        }
    }
    __syncthreads();
    float lsum = 0.f, lsq = 0.f;
    for (int o = t; o < 392; o += 256) {
        int ny = o / 49, m = o - ny*49;
        int n = n0 + ny;
        float in[24];
        #pragma unroll
        for (int c = 0; c < 24; c++) in[c] = dws[(ny*24 + c)*49 + m];
        size_t ob = ((size_t)b*3136 + n)*392 + m;
        #pragma unroll
        for (int h = 0; h < 8; h++) {
            float r = 0.f;
            #pragma unroll
            for (int c = 0; c < 24; c++) r += in[c] * rw[h*24 + c];
            __nv_bfloat16 hh, ll; bsplit(r, hh, ll);
            g_ath[ob + h*49] = hh;
            g_atl[ob + h*49] = ll;
            lsum += r; lsq += r*r;
        }
    }
    red[t] = lsum; red[256 + t] = lsq;
    __syncthreads();
    for (int st = 128; st; st >>= 1) {
        if (t < st) { red[t] += red[t+st]; red[256+t] += red[256+t+st]; }
        __syncthreads();
    }
    if (!t) {
        g_part3[(b*392 + nt)*2]     = red[0];
        g_part3[(b*392 + nt)*2 + 1] = red[256];
    }
}

// ---------------- 8. k_wvpfin: fused wvpsplit (blocks 0..3327) + wvpbias (3328..3343) ----------------
__global__ __launch_bounds__(256) void k_wvpfin(const float* __restrict__ proj_b) {
    __shared__ float tile[32][33];
    int blk = blockIdx.x;
    int t = threadIdx.x;
    if (blk < 3328) {
        int tj = blk % 13;
        int rest = blk / 13;
        int tc = rest & 15, b = rest >> 4;
        int a = t >> 5, q = t & 31;
        #pragma unroll
        for (int r = 0; r < 4; r++) {
            int jj = tj*32 + a + r*8, cc = tc*32 + q;
            float v = 0.f;
            if (jj < 392) v = g_Wvp[((size_t)b*392 + jj)*512 + cc] * g_ab3[(b*8 + jj/49)*2];
            tile[a + r*8][q] = v;
        }
        __syncthreads();
        #pragma unroll
        for (int r = 0; r < 4; r++) {
            int cc = tc*32 + a + r*8, jj = tj*32 + q;
            if (jj < 392) {
                float v = tile[q][a + r*8];
                __nv_bfloat16 h, l; bsplit(v, h, l);
                size_t o = ((size_t)b*512 + cc)*392 + jj;
                g_wvh[o] = h; g_wvl[o] = l;
            }
        }
    } else {
        int b = blk - 3328;
        #pragma unroll
        for (int cc = 0; cc < 2; cc++) {
            int c = t + cc*256;
            float acc = 0.f;
            for (int j = 0; j < 392; j++)
                acc += g_ab3[(b*8 + j/49)*2 + 1] * g_Wvp[((size_t)b*392 + j)*512 + c];
            g_bias2[b*512 + c] = acc + proj_b[c];
        }
    }
}

// ---------------- 9. GEMM2 (bf16x3 mma.sync) ----------------
#define G2_BUF 15360
#define G2_AH 0
#define G2_AL 5120
#define G2_BH 10240
#define G2_BL 12800
#define G2_SMEM (G2_BUF*2*2)
__device__ __forceinline__ void g2_load(uint32_t sb, int b, int nt0, int ct0,
                                        int kt, int p, int t) {
    int k0 = kt*32;
    uint32_t base = sb + (uint32_t)p*G2_BUF*2;
    #pragma unroll
    for (int rr = 0; rr < 2; rr++) {
        int idx = t + rr*256;
        int row = idx >> 2, q = idx & 3;
        int n = nt0 + row, j0 = k0 + q*8;
        bool v = (n < 3136) && (j0 < 392);
        size_t e = ((size_t)b*3136 + (n < 3136 ? n : 0))*392 + (j0 < 392 ? j0 : 0);
        uint32_t doff = (uint32_t)(row*40 + q*8)*2;
        cpa16(base + G2_AH*2 + doff, g_ath + e, v);
        cpa16(base + G2_AL*2 + doff, g_atl + e, v);
    }
    {
        int idx = t;
        int row = idx >> 2, q = idx & 3;
        int c = ct0 + row, j0 = k0 + q*8;
        bool v = j0 < 392;
        size_t e = ((size_t)b*512 + c)*392 + (v ? j0 : 0);
        uint32_t doff = (uint32_t)(row*40 + q*8)*2;
        cpa16(base + G2_BH*2 + doff, g_wvh + e, v);
        cpa16(base + G2_BL*2 + doff, g_wvl + e, v);
    }
}

__global__ __launch_bounds__(256) void k_gemm2_mma(float* __restrict__ out) {
    extern __shared__ __nv_bfloat16 dsm2[];
    uint32_t sb = smem_u32(dsm2);
    int b = blockIdx.z, nt0 = blockIdx.y*128, ct0 = blockIdx.x*64;
    int t = threadIdx.x, w = t >> 5, lane = t & 31;
    int wn = (w & 3)*32, wc = (w >> 2)*32;
    float acc[2][4][4];
    #pragma unroll
    for (int i = 0; i < 2; i++)
        #pragma unroll
        for (int j = 0; j < 4; j++)
            #pragma unroll
            for (int k = 0; k < 4; k++) acc[i][j][k] = 0.f;

    g2_load(sb, b, nt0, ct0, 0, 0, t);
    cp_commit();
    for (int kt = 0; kt < 13; kt++) {
        if (kt < 12) {
            g2_load(sb, b, nt0, ct0, kt+1, (kt+1) & 1, t);
            cp_commit();
            cp_wait1();
        } else cp_wait0();
        __syncthreads();
        uint32_t base = sb + (uint32_t)(kt & 1)*G2_BUF*2;
        #pragma unroll
        for (int kk = 0; kk < 2; kk++) {
            int kb = kk*16;
            uint32_t ah[2][4], al[2][4];
            #pragma unroll
            for (int mt = 0; mt < 2; mt++) {
                int row = wn + mt*16 + (lane & 15);
                int col = kb + ((lane & 16) ? 8 : 0);
                uint32_t off = (uint32_t)(row*40 + col)*2;
                ldm_x4(ah[mt], base + G2_AH*2 + off);
                ldm_x4(al[mt], base + G2_AL*2 + off);
            }
            uint32_t bh[4][2], bl[4][2];
            #pragma unroll
            for (int p = 0; p < 2; p++) {
                int crow = wc + p*16 + (lane & 7) + ((lane & 16) ? 8 : 0);
                int col = kb + ((lane & 8) ? 8 : 0);
                uint32_t off = (uint32_t)(crow*40 + col)*2;
                uint32_t r4[4];
                ldm_x4(r4, base + G2_BH*2 + off);
                bh[2*p][0]=r4[0]; bh[2*p][1]=r4[1]; bh[2*p+1][0]=r4[2]; bh[2*p+1][1]=r4[3];
                ldm_x4(r4, base + G2_BL*2 + off);
                bl[2*p][0]=r4[0]; bl[2*p][1]=r4[1]; bl[2*p+1][0]=r4[2]; bl[2*p+1][1]=r4[3];
            }
            #pragma unroll
            for (int mt = 0; mt < 2; mt++)
                #pragma unroll
                for (int ct = 0; ct < 4; ct++) {
                    mma_bf16(acc[mt][ct], ah[mt], bh[ct]);
                    mma_bf16(acc[mt][ct], al[mt], bh[ct]);
                    mma_bf16(acc[mt][ct], ah[mt], bl[ct]);
                }
        }
        __syncthreads();
    }
    int nrow = nt0 + wn + (lane >> 2);
    #pragma unroll
    for (int mt = 0; mt < 2; mt++) {
        #pragma unroll
        for (int ct = 0; ct < 4; ct++) {
            int c0 = ct0 + wc + ct*8 + ((lane & 3) << 1);
            float b0 = g_bias2[b*512 + c0];
            float b1 = g_bias2[b*512 + c0 + 1];
            #pragma unroll
            for (int half = 0; half < 2; half++) {
                int n = nrow + mt*16 + half*8;
                if (n < 3136) {
                    size_t o = ((size_t)b*3136 + n)*512 + c0;
                    *(float2*)&out[o] = make_float2(acc[mt][ct][half*2] + b0,
                                                    acc[mt][ct][half*2+1] + b1);
                }
            }
        }
    }
}

// ---------------- launcher ----------------
extern "C" void kernel_launch(void* const* d_in, const int* in_sizes, int n_in,
                              void* d_out, int out_size) {
    const float* x        = (const float*)d_in[0];
    const float* q_w      = (const float*)d_in[1];
    const float* down_w   = (const float*)d_in[2];
    const float* kv_w     = (const float*)d_in[3];
    const float* proj_w   = (const float*)d_in[4];
    const float* proj_b   = (const float*)d_in[5];
    const float* rel_bias = (const float*)d_in[6];
    const float* expand_w = (const float*)d_in[7];
    const float* gn1_s    = (const float*)d_in[8];
    const float* gn1_b    = (const float*)d_in[9];
    const float* dw_w     = (const float*)d_in[10];
    const float* gn2_s    = (const float*)d_in[11];
    const float* gn2_b    = (const float*)d_in[12];
    const float* reduce_w = (const float*)d_in[13];
    const float* gn3_s    = (const float*)d_in[14];
    const float* gn3_b    = (const float*)d_in[15];
    float* out = (float*)d_out;

    float *ab2, *ab3, *p2, *p3;
    cudaGetSymbolAddress((void**)&ab2, g_ab2);
    cudaGetSymbolAddress((void**)&ab3, g_ab3);
    cudaGetSymbolAddress((void**)&p2, g_part2);
    cudaGetSymbolAddress((void**)&p3, g_part3);

    cudaFuncSetAttribute(k_gemm1_fused, cudaFuncAttributeMaxDynamicSharedMemorySize, G1_SMEM);
    cudaFuncSetAttribute(k_gemm2_mma, cudaFuncAttributeMaxDynamicSharedMemorySize, G2_SMEM);
    cudaFuncSetAttribute(k_dw_gn2,    cudaFuncAttributeMaxDynamicSharedMemorySize, B2_SMEM);
    cudaFuncSetAttribute(k_dla_out,   cudaFuncAttributeMaxDynamicSharedMemorySize, C2_SMEM);

    k_prep<<<33280, 256>>>(x, down_w);
    k_kv  <<<dim3(4, 7, BB), 256>>>(kv_w);
    k_qkvw<<<1152, 256>>>(q_w, proj_w);
    k_gemm1_fused<<<dim3(98, BB), 256, G1_SMEM>>>(rel_bias);
    k_gn1_final<<<BB, 64>>>(gn1_s, gn1_b, expand_w);
    k_dw_gn2<<<dim3(196, BB), 256, B2_SMEM>>>(dw_w, expand_w);
    k_stats_final<<<BB*3, 256>>>(gn2_s, gn2_b, ab2, p2, 3, 196);
    k_dla_out<<<dim3(392, BB), 256, C2_SMEM>>>(dw_w, expand_w, reduce_w);
    k_stats_final<<<BB, 256>>>(gn3_s, gn3_b, ab3, p3, 1, 392);
    k_wvpfin<<<3344, 256>>>(proj_b);
    k_gemm2_mma<<<dim3(8, 25, BB), 256, G2_SMEM>>>(out);
}